// round 2
// baseline (speedup 1.0000x reference)
#include <cuda_runtime.h>
#include <math.h>

// ---------------- problem constants ----------------
// N=NQ=2048, NY=16, L=8, D=768, NIN=6144, H=512, NH=4096, G=64, nh=64
#define CN   2048
#define CNY  16
#define CL   8
#define CD   768
#define CNIN 6144
#define CH   512
#define CNH  4096
#define CG   64
#define CV   50257

// ---------------- device scratch (no runtime allocation allowed) ----------------
__device__ __align__(16) float g_e [CN * CNIN];          // 50.3 MB embedding buffer (reused x / qx)
__device__ __align__(16) float g_h1[CN * CH];
__device__ __align__(16) float g_h2[CN * CH];
__device__ __align__(16) float g_X [CN * CNH];           // train embeddings (normalized in place)
__device__ __align__(16) float g_XQ[CN * CNH];           // query embeddings (raw; xmul folded into w/cov)
__device__ __align__(16) float g_xmul[CNH];
__device__ __align__(16) float g_Yc[CN * CNY];
__device__ __align__(16) float g_ymul[CNY];
__device__ __align__(16) float g_bmean[CNY];
__device__ __align__(16) float g_ycss[CNY];
__device__ __align__(16) float g_scal[2];                // {reg, t}
__device__ __align__(16) float g_Mpart[4][CG * 64 * 64]; // split-K Gram partials
__device__ __align__(16) float g_apart[8][CNH * CNY];    // split-K X^T Yc partials
__device__ __align__(16) float g_cov [CG * 64 * 64];
__device__ __align__(16) float g_covv[CG * 64 * 64];     // cov folded with 1/xmul
__device__ __align__(16) float g_S[CG];
__device__ __align__(16) float g_w0[CNH * CNY];
__device__ __align__(16) float g_cw[CNH * CNY];
__device__ __align__(16) float g_p [CG * CNY];
__device__ __align__(16) float g_w [CNH * CNY];          // w0*p/xmul
__device__ int g_tok64;                                  // 1 if token buffer is int64

// ---------------- token dtype detection ----------------
// If tokens are little-endian int64 (< 2^31), every odd int32 word is zero.
// If tokens are int32 (random in [0, 50257)), essentially surely some odd word != 0.
__global__ void k_detect(const int* __restrict__ t, int n_elems) {
    __shared__ int nz;
    if (threadIdx.x == 0) nz = 0;
    __syncthreads();
    int local = 0;
    for (int i = 2 * threadIdx.x + 1; i < n_elems; i += 2 * 256)
        if (t[i] != 0) local = 1;
    if (local) atomicOr(&nz, 1);
    __syncthreads();
    if (threadIdx.x == 0) g_tok64 = (nz == 0) ? 1 : 0;
}

// ---------------- scalars ----------------
__global__ void k_scal(const float* __restrict__ rp, const float* __restrict__ tp) {
    g_scal[0] = expf(rp[0]) + 1e-8f;
    g_scal[1] = expf(tp[0]) + 1e-8f;
}

// ---------------- y stats: ymul, b, Yc, sum(Yc^2) ----------------
__global__ void k_ystats(const float* __restrict__ y) {
    int j = blockIdx.x, tid = threadIdx.x;
    __shared__ float red[256];
    __shared__ float sh_ym, sh_b;
    float s = 0.f, ss = 0.f;
    for (int n = tid; n < CN; n += 256) { float v = y[n * CNY + j]; s += v; ss += v * v; }
    red[tid] = s; __syncthreads();
    for (int st = 128; st; st >>= 1) { if (tid < st) red[tid] += red[tid + st]; __syncthreads(); }
    float S = red[0]; __syncthreads();
    red[tid] = ss; __syncthreads();
    for (int st = 128; st; st >>= 1) { if (tid < st) red[tid] += red[tid + st]; __syncthreads(); }
    float SS = red[0]; __syncthreads();
    if (tid == 0) {
        float var = (SS - S * S / (float)CN) / (float)(CN - 1);
        float ym = sqrtf(fmaxf(var, 0.f)) + 0.1f;
        float b = (S / (float)CN) / ym;
        sh_ym = ym; sh_b = b;
        g_ymul[j] = ym; g_bmean[j] = b;
    }
    __syncthreads();
    float ym = sh_ym, b = sh_b;
    float cs = 0.f;
    for (int n = tid; n < CN; n += 256) {
        float v = y[n * CNY + j] / ym - b;
        g_Yc[n * CNY + j] = v;
        cs += v * v;
    }
    red[tid] = cs; __syncthreads();
    for (int st = 128; st; st >>= 1) { if (tid < st) red[tid] += red[tid + st]; __syncthreads(); }
    if (tid == 0) g_ycss[j] = red[0];
}

// ---------------- gather: e[r, l*768+c] = we[tok[r,l], c] (float4) ----------------
__global__ void k_gather(const void* __restrict__ tok,
                         const float4* __restrict__ we4, float4* __restrict__ e4) {
    int idx = blockIdx.x * 256 + threadIdx.x;       // over CN*1536 float4
    if (idx >= CN * (CNIN / 4)) return;
    int r = idx / (CNIN / 4), k4 = idx - r * (CNIN / 4);
    int l = k4 / (CD / 4), c4 = k4 - l * (CD / 4);
    long long t;
    if (g_tok64) t = ((const long long*)tok)[r * CL + l];
    else         t = (long long)((const int*)tok)[r * CL + l];
    if (t < 0) t = 0;
    if (t >= CV) t = CV - 1;
    e4[idx] = we4[(size_t)t * (CD / 4) + c4];
}

// ---------------- tiled SGEMM, C[M,N] = A[M,K] @ B[N,K]^T (+bias, optional relu) ----
template <int BM, int BN, int BK, int TM, int TN>
__global__ __launch_bounds__(256) void k_gemm_nt(
    const float* __restrict__ A, const float* __restrict__ B,
    const float* __restrict__ bias, float* __restrict__ C,
    int M, int Nn, int K, int doRelu)
{
    constexpr int SA = BM + 4, SB = BN + 4;
    __shared__ float As[BK][SA];
    __shared__ float Bs[BK][SB];
    const int tid = threadIdx.x;
    const int m0 = blockIdx.y * BM, n0 = blockIdx.x * BN;
    constexpr int TX = BN / TN;
    const int tm = tid / TX, tn = tid % TX;
    const int rowBase = tm * TM, colBase = tn * TN;
    constexpr int K4 = BK / 4;
    constexpr int A4 = BM * BK / 4;
    constexpr int B4 = BN * BK / 4;
    float acc[TM][TN] = {};
    for (int k0 = 0; k0 < K; k0 += BK) {
#pragma unroll
        for (int it = 0; it < A4 / 256; ++it) {
            int idx = tid + it * 256;
            int r = idx / K4, c4 = idx - r * K4;
            float4 v = *(const float4*)&A[(size_t)(m0 + r) * K + k0 + c4 * 4];
            As[c4 * 4 + 0][r] = v.x; As[c4 * 4 + 1][r] = v.y;
            As[c4 * 4 + 2][r] = v.z; As[c4 * 4 + 3][r] = v.w;
        }
#pragma unroll
        for (int it = 0; it < B4 / 256; ++it) {
            int idx = tid + it * 256;
            int r = idx / K4, c4 = idx - r * K4;
            float4 v = *(const float4*)&B[(size_t)(n0 + r) * K + k0 + c4 * 4];
            Bs[c4 * 4 + 0][r] = v.x; Bs[c4 * 4 + 1][r] = v.y;
            Bs[c4 * 4 + 2][r] = v.z; Bs[c4 * 4 + 3][r] = v.w;
        }
        __syncthreads();
#pragma unroll
        for (int kk = 0; kk < BK; ++kk) {
            float a[TM], b[TN];
#pragma unroll
            for (int i = 0; i < TM; i += 4)
                *(float4*)&a[i] = *(const float4*)&As[kk][rowBase + i];
#pragma unroll
            for (int j = 0; j < TN; j += 4)
                *(float4*)&b[j] = *(const float4*)&Bs[kk][colBase + j];
#pragma unroll
            for (int i = 0; i < TM; ++i)
#pragma unroll
                for (int j = 0; j < TN; ++j)
                    acc[i][j] = fmaf(a[i], b[j], acc[i][j]);
        }
        __syncthreads();
    }
    float bb[TN];
#pragma unroll
    for (int j = 0; j < TN; ++j) bb[j] = bias[n0 + colBase + j];
#pragma unroll
    for (int i = 0; i < TM; ++i) {
        size_t off = (size_t)(m0 + rowBase + i) * Nn + n0 + colBase;
#pragma unroll
        for (int j0 = 0; j0 < TN; j0 += 4) {
            float4 o;
            o.x = acc[i][j0 + 0] + bb[j0 + 0];
            o.y = acc[i][j0 + 1] + bb[j0 + 1];
            o.z = acc[i][j0 + 2] + bb[j0 + 2];
            o.w = acc[i][j0 + 3] + bb[j0 + 3];
            if (doRelu) {
                o.x = fmaxf(o.x, 0.f); o.y = fmaxf(o.y, 0.f);
                o.z = fmaxf(o.z, 0.f); o.w = fmaxf(o.w, 0.f);
            }
            *(float4*)&C[off + j0] = o;
        }
    }
}

// ---------------- per-column std of X -> xmul ----------------
__global__ void k_xstats() {
    int c = blockIdx.x * 256 + threadIdx.x;   // 4096 columns
    float s[8] = {}, ss[8] = {};
    for (int n = 0; n < CN; n += 8) {
#pragma unroll
        for (int u = 0; u < 8; ++u) {
            float v = g_X[(size_t)(n + u) * CNH + c];
            s[u] += v; ss[u] += v * v;
        }
    }
    double S = 0.0, SS = 0.0;
#pragma unroll
    for (int u = 0; u < 8; ++u) { S += (double)s[u]; SS += (double)ss[u]; }
    double var = (SS - S * S / (double)CN) / (double)(CN - 1);
    if (var < 0.0) var = 0.0;
    g_xmul[c] = (float)sqrt(var) + 0.1f;
}

__global__ void k_xnorm() {
    size_t idx = (size_t)blockIdx.x * 256 + threadIdx.x;
    g_X[idx] = g_X[idx] / g_xmul[idx & (CNH - 1)];
}

// ---------------- Gram partials: Mpart[s][g] = sum_n Xg^T Xg over n-slice ---------
__global__ __launch_bounds__(256) void k_cov() {
    int g = blockIdx.x, sp = blockIdx.y, tid = threadIdx.x;
    __shared__ float tile[32][68];
    const int ti = (tid & 15) * 4, tj = (tid >> 4) * 4;
    float acc[4][4] = {};
    for (int n0 = sp * 512; n0 < sp * 512 + 512; n0 += 32) {
#pragma unroll
        for (int it = 0; it < 2; ++it) {
            int idx = tid + it * 256;
            int r = idx >> 4, c4 = idx & 15;
            float4 v = *(const float4*)&g_X[(size_t)(n0 + r) * CNH + g * 64 + c4 * 4];
            *(float4*)&tile[r][c4 * 4] = v;
        }
        __syncthreads();
#pragma unroll 4
        for (int r = 0; r < 32; ++r) {
            float xi[4], xj[4];
            *(float4*)xi = *(const float4*)&tile[r][ti];
            *(float4*)xj = *(const float4*)&tile[r][tj];
#pragma unroll
            for (int a = 0; a < 4; ++a)
#pragma unroll
                for (int b = 0; b < 4; ++b)
                    acc[a][b] = fmaf(xi[a], xj[b], acc[a][b]);
        }
        __syncthreads();
    }
    float* out = &g_Mpart[sp][g * 4096];
#pragma unroll
    for (int a = 0; a < 4; ++a)
#pragma unroll
        for (int b = 0; b < 4; ++b)
            out[(ti + a) * 64 + (tj + b)] = acc[a][b];
}

// ---------------- a partials: apart[s] = X^T Yc over n-slice ----------------
__global__ __launch_bounds__(256) void k_apart() {
    int c = blockIdx.x * 256 + threadIdx.x;
    int sp = blockIdx.y;
    int n0 = sp * 256;
    __shared__ float ys[256 * CNY];
    for (int i = threadIdx.x; i < 256 * CNY; i += 256) ys[i] = g_Yc[n0 * CNY + i];
    __syncthreads();
    float acc[CNY] = {};
    for (int n = 0; n < 256; ++n) {
        float v = g_X[(size_t)(n0 + n) * CNH + c];
#pragma unroll
        for (int j = 0; j < CNY; ++j) acc[j] = fmaf(v, ys[n * CNY + j], acc[j]);
    }
#pragma unroll
    for (int j = 0; j < CNY; ++j) g_apart[sp][c * CNY + j] = acc[j];
}

// ---------------- Cholesky + logdet + inverse per group (fp32) ----------------
__global__ __launch_bounds__(64) void k_chol() {
    int g = blockIdx.x, tid = threadIdx.x;
    __shared__ float A[64][65];
    __shared__ float Yv[64][64];
    float rg = g_scal[0], t = g_scal[1];
    for (int i = 0; i < 64; ++i) {
        float m = 0.f;
#pragma unroll
        for (int sp = 0; sp < 4; ++sp) m += g_Mpart[sp][g * 4096 + i * 64 + tid];
        A[i][tid] = t * m + (i == tid ? rg : 0.f);
    }
    __syncthreads();
    for (int k = 0; k < 64; ++k) {
        float akk = A[k][k];
        float skk = sqrtf(akk);
        __syncthreads();
        if (tid == k) A[k][k] = skk;
        else if (tid > k) A[tid][k] = A[tid][k] / skk;
        __syncthreads();
        if (tid > k) {
            float lik = A[tid][k];
            for (int j = k + 1; j <= tid; ++j) A[tid][j] -= lik * A[j][k];
        }
        __syncthreads();
    }
    if (tid == 0) {
        float s = 0.f;
        for (int i = 0; i < 64; ++i) s += logf(A[i][i]);
        g_S[g] = 2.f * s;
    }
    // inverse: column tid. forward solve L y = e_c, then back solve L^T z = y.
    const int c = tid;
    for (int i = 0; i < 64; ++i) {
        if (i < c) { Yv[i][c] = 0.f; continue; }
        float s = (i == c) ? 1.f : 0.f;
        for (int j = c; j < i; ++j) s -= A[i][j] * Yv[j][c];
        Yv[i][c] = s / A[i][i];
    }
    for (int i = 63; i >= 0; --i) {
        float s = Yv[i][c];
        for (int j = i + 1; j < 64; ++j) s -= A[j][i] * Yv[j][c];
        Yv[i][c] = s / A[i][i];
    }
    __syncthreads();
    for (int i = 0; i < 64; ++i) g_cov[g * 4096 + i * 64 + c] = Yv[i][c];
}

// ---------------- w0 = t*cov@a ; cw = cov@w0 ----------------
__global__ __launch_bounds__(256) void k_w0cw() {
    int g = blockIdx.x, tid = threadIdx.x;
    __shared__ float covs[64][65];
    __shared__ float as[64][17];
    __shared__ float w0s[64][17];
    for (int idx = tid; idx < 4096; idx += 256)
        covs[idx >> 6][idx & 63] = g_cov[g * 4096 + idx];
    for (int idx = tid; idx < 64 * CNY; idx += 256) {
        int i = idx >> 4, j = idx & 15;
        float s = 0.f;
#pragma unroll
        for (int sp = 0; sp < 8; ++sp) s += g_apart[sp][(g * 64 + i) * CNY + j];
        as[i][j] = s;
    }
    __syncthreads();
    float t = g_scal[1];
    int j = tid & 15, i0 = (tid >> 4) * 4;
#pragma unroll
    for (int ii = 0; ii < 4; ++ii) {
        float s = 0.f;
        for (int k = 0; k < 64; ++k) s = fmaf(covs[i0 + ii][k], as[k][j], s);
        w0s[i0 + ii][j] = t * s;
    }
    __syncthreads();
#pragma unroll
    for (int ii = 0; ii < 4; ++ii) {
        float s = 0.f;
        for (int k = 0; k < 64; ++k) s = fmaf(covs[i0 + ii][k], w0s[k][j], s);
        g_cw[(g * 64 + i0 + ii) * CNY + j] = s;
        g_w0[(g * 64 + i0 + ii) * CNY + j] = w0s[i0 + ii][j];
    }
}

// ---------------- softmax over groups -> p ----------------
__global__ __launch_bounds__(1024) void k_p() {
    int tid = threadIdx.x;
    int g = tid >> 4, j = tid & 15;
    float corr = 0.f;
    for (int i = 0; i < 64; ++i)
        corr = fmaf(g_w0[(g * 64 + i) * CNY + j], g_cw[(g * 64 + i) * CNY + j], corr);
    float t = g_scal[1];
    float lg = corr - t * g_ycss[j] - g_S[g];
    __shared__ float L[64][17];
    __shared__ float mx[16], sm[16];
    L[g][j] = lg;
    __syncthreads();
    if (tid < 16) {
        float m = -1e30f;
        for (int gg = 0; gg < 64; ++gg) m = fmaxf(m, L[gg][tid]);
        float s = 0.f;
        for (int gg = 0; gg < 64; ++gg) s += expf(L[gg][tid] - m);
        mx[tid] = m; sm[tid] = s;
    }
    __syncthreads();
    g_p[g * CNY + j] = expf(lg - mx[j]) / sm[j];
}

// ---------------- fold xmul into w and cov ----------------
__global__ void k_wprime() {
    int idx = blockIdx.x * 256 + threadIdx.x;     // 65536
    int c = idx >> 4, j = idx & 15;
    g_w[idx] = g_w0[idx] * g_p[(c >> 6) * CNY + j] / g_xmul[c];
}
__global__ void k_covv() {
    int idx = blockIdx.x * 256 + threadIdx.x;     // 262144
    int g = idx >> 12, i = (idx >> 6) & 63, j = idx & 63;
    g_covv[idx] = g_cov[idx] / (g_xmul[g * 64 + i] * g_xmul[g * 64 + j]);
}

// ---------------- fused predict: qy and qy_std ----------------
__global__ __launch_bounds__(128) void k_predict(float* __restrict__ out) {
    const int tid = threadIdx.x;
    const int r = tid >> 3, lane = tid & 7;
    const int row0 = blockIdx.x * 16;
    __shared__ float Xs[16][65];
    __shared__ float Cs[64][65];
    __shared__ float Ws[64][17];
    __shared__ float ps[16];
    float accy[CNY] = {};
    float v0 = 0.f, v1 = 0.f;
    for (int g = 0; g < CG; ++g) {
#pragma unroll
        for (int it = 0; it < 8; ++it) {
            int idx = tid + it * 128;
            Xs[idx >> 6][idx & 63] = g_XQ[(size_t)(row0 + (idx >> 6)) * CNH + g * 64 + (idx & 63)];
        }
#pragma unroll
        for (int it = 0; it < 32; ++it) {
            int idx = tid + it * 128;
            Cs[idx >> 6][idx & 63] = g_covv[g * 4096 + idx];
        }
#pragma unroll
        for (int it = 0; it < 8; ++it) {
            int idx = tid + it * 128;
            Ws[idx >> 4][idx & 15] = g_w[(g * 64 + (idx >> 4)) * CNY + (idx & 15)];
        }
        if (tid < 16) ps[tid] = g_p[g * CNY + tid];
        __syncthreads();
        float x[8];
#pragma unroll
        for (int ii = 0; ii < 8; ++ii) x[ii] = Xs[r][lane * 8 + ii];
#pragma unroll
        for (int ii = 0; ii < 8; ++ii)
#pragma unroll
            for (int j = 0; j < CNY; ++j)
                accy[j] = fmaf(x[ii], Ws[lane * 8 + ii][j], accy[j]);
        float s = 0.f;
        for (int jc = 0; jc < 64; ++jc) {
            float xj = Xs[r][jc];
            float q = 0.f;
#pragma unroll
            for (int ii = 0; ii < 8; ++ii) q = fmaf(Cs[lane * 8 + ii][jc], x[ii], q);
            s = fmaf(q, xj, s);
        }
        s += __shfl_xor_sync(0xffffffffu, s, 4);
        s += __shfl_xor_sync(0xffffffffu, s, 2);
        s += __shfl_xor_sync(0xffffffffu, s, 1);
        v0 = fmaf(s, ps[lane * 2 + 0], v0);
        v1 = fmaf(s, ps[lane * 2 + 1], v1);
        __syncthreads();
    }
#pragma unroll
    for (int j = 0; j < CNY; ++j) {
        accy[j] += __shfl_xor_sync(0xffffffffu, accy[j], 4);
        accy[j] += __shfl_xor_sync(0xffffffffu, accy[j], 2);
        accy[j] += __shfl_xor_sync(0xffffffffu, accy[j], 1);
    }
    const int row = row0 + r;
    const int j0 = lane * 2, j1 = j0 + 1;
    out[row * CNY + j0] = (accy[j0] + g_bmean[j0]) * g_ymul[j0];
    out[row * CNY + j1] = (accy[j1] + g_bmean[j1]) * g_ymul[j1];
    out[CN * CNY + row * CNY + j0] = sqrtf(fmaxf(v0, 0.f)) * g_ymul[j0];
    out[CN * CNY + row * CNY + j1] = sqrtf(fmaxf(v1, 0.f)) * g_ymul[j1];
}

// ---------------- launcher ----------------
extern "C" void kernel_launch(void* const* d_in, const int* in_sizes, int n_in,
                              void* d_out, int out_size) {
    const void* x  = d_in[0];
    const float* y = (const float*)d_in[1];
    const void* qx = d_in[2];
    const float* we = (const float*)d_in[3];
    const float* W1 = (const float*)d_in[4];
    const float* b1 = (const float*)d_in[5];
    const float* W2 = (const float*)d_in[6];
    const float* b2 = (const float*)d_in[7];
    const float* W3 = (const float*)d_in[8];
    const float* b3 = (const float*)d_in[9];
    const float* rp = (const float*)d_in[10];
    const float* tp = (const float*)d_in[11];
    float* out = (float*)d_out;

    float *pe, *ph1, *ph2, *pX, *pXQ;
    cudaGetSymbolAddress((void**)&pe,  g_e);
    cudaGetSymbolAddress((void**)&ph1, g_h1);
    cudaGetSymbolAddress((void**)&ph2, g_h2);
    cudaGetSymbolAddress((void**)&pX,  g_X);
    cudaGetSymbolAddress((void**)&pXQ, g_XQ);

    k_detect<<<1, 256>>>((const int*)x, in_sizes[0]);
    k_scal<<<1, 1>>>(rp, tp);
    k_ystats<<<16, 256>>>(y);

    const int gatherBlocks = (CN * (CNIN / 4) + 255) / 256;

    // embed train tokens -> g_X
    k_gather<<<gatherBlocks, 256>>>(x, (const float4*)we, (float4*)pe);
    k_gemm_nt<128, 64, 16, 8, 4><<<dim3(CH / 64, CN / 128), 256>>>(pe, W1, b1, ph1, CN, CH, CNIN, 1);
    k_gemm_nt<128, 64, 16, 8, 4><<<dim3(CH / 64, CN / 128), 256>>>(ph1, W2, b2, ph2, CN, CH, CH, 1);
    k_gemm_nt<128, 128, 16, 8, 8><<<dim3(CNH / 128, CN / 128), 256>>>(ph2, W3, b3, pX, CN, CNH, CH, 0);

    // embed query tokens -> g_XQ
    k_gather<<<gatherBlocks, 256>>>(qx, (const float4*)we, (float4*)pe);
    k_gemm_nt<128, 64, 16, 8, 4><<<dim3(CH / 64, CN / 128), 256>>>(pe, W1, b1, ph1, CN, CH, CNIN, 1);
    k_gemm_nt<128, 64, 16, 8, 4><<<dim3(CH / 64, CN / 128), 256>>>(ph1, W2, b2, ph2, CN, CH, CH, 1);
    k_gemm_nt<128, 128, 16, 8, 8><<<dim3(CNH / 128, CN / 128), 256>>>(ph2, W3, b3, pXQ, CN, CNH, CH, 0);

    // ridge learn
    k_xstats<<<CNH / 256, 256>>>();
    k_xnorm<<<(CN * CNH) / 256, 256>>>();
    k_cov<<<dim3(CG, 4), 256>>>();
    k_apart<<<dim3(CNH / 256, 8), 256>>>();
    k_chol<<<CG, 64>>>();
    k_w0cw<<<CG, 256>>>();
    k_p<<<1, 1024>>>();
    k_wprime<<<(CNH * CNY) / 256, 256>>>();
    k_covv<<<(CG * 64 * 64) / 256, 256>>>();

    // fused predict (qy + qy_std)
    k_predict<<<CN / 16, 128>>>(out);
}

// round 3
// speedup vs baseline: 1.3073x; 1.3073x over previous
#include <cuda_runtime.h>
#include <math.h>
#include <stdint.h>

// ---------------- problem constants ----------------
// N=NQ=2048, NY=16, L=8, D=768, NIN=6144, H=512, NH=4096, G=64, nh=64
#define CN   2048
#define CNY  16
#define CL   8
#define CD   768
#define CNIN 6144
#define CH   512
#define CNH  4096
#define CG   64
#define CV   50257

// ---------------- device scratch (no runtime allocation allowed) ----------------
__device__ __align__(16) float g_e [CN * CNIN];          // 50.3 MB embedding buffer (reused x / qx)
__device__ __align__(16) float g_h1[CN * CH];
__device__ __align__(16) float g_h2[CN * CH];
__device__ __align__(16) float g_X [CN * CNH];           // train embeddings (normalized in place)
__device__ __align__(16) float g_XQ[CN * CNH];           // query embeddings (raw; xmul folded into w/cov)
__device__ __align__(16) float g_xmul[CNH];
__device__ __align__(16) float g_Yc[CN * CNY];
__device__ __align__(16) float g_ymul[CNY];
__device__ __align__(16) float g_bmean[CNY];
__device__ __align__(16) float g_ycss[CNY];
__device__ __align__(16) float g_scal[2];                // {reg, t}
__device__ __align__(16) float g_Mpart[4][CG * 64 * 64]; // split-K Gram partials
__device__ __align__(16) float g_apart[8][CNH * CNY];    // split-K X^T Yc partials
__device__ __align__(16) float g_cov [CG * 64 * 64];
__device__ __align__(16) float g_covv[CG * 64 * 64];     // cov folded with 1/xmul
__device__ __align__(16) float g_S[CG];
__device__ __align__(16) float g_w0[CNH * CNY];
__device__ __align__(16) float g_cw[CNH * CNY];
__device__ __align__(16) float g_p [CG * CNY];
__device__ __align__(16) float g_w [CNH * CNY];          // w0*p/xmul
__device__ int g_tok64;                                  // 1 if token buffer is int64

// ---------------- token dtype detection ----------------
__global__ void k_detect(const int* __restrict__ t, int n_elems) {
    __shared__ int nz;
    if (threadIdx.x == 0) nz = 0;
    __syncthreads();
    int local = 0;
    for (int i = 2 * threadIdx.x + 1; i < n_elems; i += 2 * 256)
        if (t[i] != 0) local = 1;
    if (local) atomicOr(&nz, 1);
    __syncthreads();
    if (threadIdx.x == 0) g_tok64 = (nz == 0) ? 1 : 0;
}

// ---------------- scalars ----------------
__global__ void k_scal(const float* __restrict__ rp, const float* __restrict__ tp) {
    g_scal[0] = expf(rp[0]) + 1e-8f;
    g_scal[1] = expf(tp[0]) + 1e-8f;
}

// ---------------- y stats ----------------
__global__ void k_ystats(const float* __restrict__ y) {
    int j = blockIdx.x, tid = threadIdx.x;
    __shared__ float red[256];
    __shared__ float sh_ym, sh_b;
    float s = 0.f, ss = 0.f;
    for (int n = tid; n < CN; n += 256) { float v = y[n * CNY + j]; s += v; ss += v * v; }
    red[tid] = s; __syncthreads();
    for (int st = 128; st; st >>= 1) { if (tid < st) red[tid] += red[tid + st]; __syncthreads(); }
    float S = red[0]; __syncthreads();
    red[tid] = ss; __syncthreads();
    for (int st = 128; st; st >>= 1) { if (tid < st) red[tid] += red[tid + st]; __syncthreads(); }
    float SS = red[0]; __syncthreads();
    if (tid == 0) {
        float var = (SS - S * S / (float)CN) / (float)(CN - 1);
        float ym = sqrtf(fmaxf(var, 0.f)) + 0.1f;
        float b = (S / (float)CN) / ym;
        sh_ym = ym; sh_b = b;
        g_ymul[j] = ym; g_bmean[j] = b;
    }
    __syncthreads();
    float ym = sh_ym, b = sh_b;
    float cs = 0.f;
    for (int n = tid; n < CN; n += 256) {
        float v = y[n * CNY + j] / ym - b;
        g_Yc[n * CNY + j] = v;
        cs += v * v;
    }
    red[tid] = cs; __syncthreads();
    for (int st = 128; st; st >>= 1) { if (tid < st) red[tid] += red[tid + st]; __syncthreads(); }
    if (tid == 0) g_ycss[j] = red[0];
}

// ---------------- gather ----------------
__global__ void k_gather(const void* __restrict__ tok,
                         const float4* __restrict__ we4, float4* __restrict__ e4) {
    int idx = blockIdx.x * 256 + threadIdx.x;
    if (idx >= CN * (CNIN / 4)) return;
    int r = idx / (CNIN / 4), k4 = idx - r * (CNIN / 4);
    int l = k4 / (CD / 4), c4 = k4 - l * (CD / 4);
    long long t;
    if (g_tok64) t = ((const long long*)tok)[r * CL + l];
    else         t = (long long)((const int*)tok)[r * CL + l];
    if (t < 0) t = 0;
    if (t >= CV) t = CV - 1;
    e4[idx] = we4[(size_t)t * (CD / 4) + c4];
}

// ---------------- tf32 round-to-nearest ----------------
__device__ __forceinline__ uint32_t f2tf32(float f) {
    uint32_t u;
    asm("cvt.rna.tf32.f32 %0, %1;" : "=r"(u) : "f"(f));
    return u;
}

// ---------------- tensor-core GEMM: C[M,N] = A[M,K] @ B[N,K]^T (+bias, relu) ------
// mma.sync m16n8k8 tf32. Block tile 128x64, BK=32, 256 threads (8 warps 2x4),
// warp tile 64x16 (mt=4 x nt=2). Fragment-layout smem: reader does vector LDS.
__global__ __launch_bounds__(256) void k_gemm_tc(
    const float* __restrict__ A, const float* __restrict__ B,
    const float* __restrict__ bias, float* __restrict__ C,
    int M, int Nn, int K, int doRelu)
{
    // Asf[bmt(8)][kc(4)][lane(32)][reg(4)]  (16KB)
    // Bsf[bnt(8)][kc(4)][lane(32)][reg(2)]  (8KB)
    __shared__ uint32_t Asf[8 * 4 * 32 * 4];
    __shared__ uint32_t Bsf[8 * 4 * 32 * 2];
    const int tid  = threadIdx.x;
    const int lane = tid & 31, wid = tid >> 5;
    const int warp_m = wid >> 2, warp_n = wid & 3;
    const int m0 = blockIdx.y * 128, n0 = blockIdx.x * 64;

    float c[4][2][4];
#pragma unroll
    for (int i = 0; i < 4; ++i)
#pragma unroll
        for (int j = 0; j < 2; ++j)
#pragma unroll
            for (int r = 0; r < 4; ++r) c[i][j][r] = 0.f;

    for (int k0 = 0; k0 < K; k0 += 32) {
        // stage A: 128x32 -> fragment layout
#pragma unroll
        for (int it = 0; it < 4; ++it) {
            int t = tid + it * 256;              // 0..1023
            int m = t >> 3, k4 = t & 7;          // k4: which float4 in the 32-wide k
            float4 v = *(const float4*)&A[(size_t)(m0 + m) * K + k0 + k4 * 4];
            int bmt = m >> 4;
            int kc = k4 >> 1;
            int reg = ((m >> 3) & 1) | ((k4 & 1) << 1);
            int ln = ((m & 7) << 2);
            uint32_t* dst = &Asf[(((bmt << 2) + kc) << 7) + (ln << 2) + reg];
            dst[0 * 4]  = f2tf32(v.x);
            dst[1 * 4]  = f2tf32(v.y);
            dst[2 * 4]  = f2tf32(v.z);
            dst[3 * 4]  = f2tf32(v.w);
        }
        // stage B: 64x32 -> fragment layout
#pragma unroll
        for (int it = 0; it < 2; ++it) {
            int t = tid + it * 256;              // 0..511
            int n = t >> 3, k4 = t & 7;
            float4 v = *(const float4*)&B[(size_t)(n0 + n) * K + k0 + k4 * 4];
            int bnt = n >> 3;
            int kc = k4 >> 1;
            int reg = k4 & 1;
            int ln = ((n & 7) << 2);
            uint32_t* dst = &Bsf[(((bnt << 2) + kc) << 6) + (ln << 1) + reg];
            dst[0 * 2] = f2tf32(v.x);
            dst[1 * 2] = f2tf32(v.y);
            dst[2 * 2] = f2tf32(v.z);
            dst[3 * 2] = f2tf32(v.w);
        }
        __syncthreads();
#pragma unroll
        for (int kc = 0; kc < 4; ++kc) {
            uint4 a[4];
            uint2 b[2];
#pragma unroll
            for (int mt = 0; mt < 4; ++mt) {
                int bmt = warp_m * 4 + mt;
                a[mt] = *(const uint4*)&Asf[(((bmt << 2) + kc) << 7) + (lane << 2)];
            }
#pragma unroll
            for (int nt = 0; nt < 2; ++nt) {
                int bnt = warp_n * 2 + nt;
                b[nt] = *(const uint2*)&Bsf[(((bnt << 2) + kc) << 6) + (lane << 1)];
            }
#pragma unroll
            for (int mt = 0; mt < 4; ++mt)
#pragma unroll
                for (int nt = 0; nt < 2; ++nt) {
                    asm volatile(
                        "mma.sync.aligned.m16n8k8.row.col.f32.tf32.tf32.f32 "
                        "{%0,%1,%2,%3}, {%4,%5,%6,%7}, {%8,%9}, {%0,%1,%2,%3};"
                        : "+f"(c[mt][nt][0]), "+f"(c[mt][nt][1]),
                          "+f"(c[mt][nt][2]), "+f"(c[mt][nt][3])
                        : "r"(a[mt].x), "r"(a[mt].y), "r"(a[mt].z), "r"(a[mt].w),
                          "r"(b[nt].x), "r"(b[nt].y));
                }
        }
        __syncthreads();
    }
    // epilogue: bias + optional relu
#pragma unroll
    for (int mt = 0; mt < 4; ++mt) {
        int row = m0 + warp_m * 64 + mt * 16 + (lane >> 2);
#pragma unroll
        for (int nt = 0; nt < 2; ++nt) {
            int col = n0 + warp_n * 16 + nt * 8 + 2 * (lane & 3);
            float b0 = bias[col], b1 = bias[col + 1];
            float v0 = c[mt][nt][0] + b0, v1 = c[mt][nt][1] + b1;
            float v2 = c[mt][nt][2] + b0, v3 = c[mt][nt][3] + b1;
            if (doRelu) {
                v0 = fmaxf(v0, 0.f); v1 = fmaxf(v1, 0.f);
                v2 = fmaxf(v2, 0.f); v3 = fmaxf(v3, 0.f);
            }
            *(float2*)&C[(size_t)row * Nn + col] = make_float2(v0, v1);
            *(float2*)&C[(size_t)(row + 8) * Nn + col] = make_float2(v2, v3);
        }
    }
}

// ---------------- per-column std of X -> xmul ----------------
__global__ void k_xstats() {
    int c = blockIdx.x * 256 + threadIdx.x;
    float s[8] = {}, ss[8] = {};
    for (int n = 0; n < CN; n += 8) {
#pragma unroll
        for (int u = 0; u < 8; ++u) {
            float v = g_X[(size_t)(n + u) * CNH + c];
            s[u] += v; ss[u] += v * v;
        }
    }
    double S = 0.0, SS = 0.0;
#pragma unroll
    for (int u = 0; u < 8; ++u) { S += (double)s[u]; SS += (double)ss[u]; }
    double var = (SS - S * S / (double)CN) / (double)(CN - 1);
    if (var < 0.0) var = 0.0;
    g_xmul[c] = (float)sqrt(var) + 0.1f;
}

__global__ void k_xnorm() {
    size_t idx = (size_t)blockIdx.x * 256 + threadIdx.x;
    g_X[idx] = g_X[idx] / g_xmul[idx & (CNH - 1)];
}

// ---------------- Gram partials ----------------
__global__ __launch_bounds__(256) void k_cov() {
    int g = blockIdx.x, sp = blockIdx.y, tid = threadIdx.x;
    __shared__ float tile[32][68];
    const int ti = (tid & 15) * 4, tj = (tid >> 4) * 4;
    float acc[4][4] = {};
    for (int n0 = sp * 512; n0 < sp * 512 + 512; n0 += 32) {
#pragma unroll
        for (int it = 0; it < 2; ++it) {
            int idx = tid + it * 256;
            int r = idx >> 4, c4 = idx & 15;
            float4 v = *(const float4*)&g_X[(size_t)(n0 + r) * CNH + g * 64 + c4 * 4];
            *(float4*)&tile[r][c4 * 4] = v;
        }
        __syncthreads();
#pragma unroll 4
        for (int r = 0; r < 32; ++r) {
            float xi[4], xj[4];
            *(float4*)xi = *(const float4*)&tile[r][ti];
            *(float4*)xj = *(const float4*)&tile[r][tj];
#pragma unroll
            for (int a = 0; a < 4; ++a)
#pragma unroll
                for (int b = 0; b < 4; ++b)
                    acc[a][b] = fmaf(xi[a], xj[b], acc[a][b]);
        }
        __syncthreads();
    }
    float* out = &g_Mpart[sp][g * 4096];
#pragma unroll
    for (int a = 0; a < 4; ++a)
#pragma unroll
        for (int b = 0; b < 4; ++b)
            out[(ti + a) * 64 + (tj + b)] = acc[a][b];
}

// ---------------- a partials ----------------
__global__ __launch_bounds__(256) void k_apart() {
    int c = blockIdx.x * 256 + threadIdx.x;
    int sp = blockIdx.y;
    int n0 = sp * 256;
    __shared__ float ys[256 * CNY];
    for (int i = threadIdx.x; i < 256 * CNY; i += 256) ys[i] = g_Yc[n0 * CNY + i];
    __syncthreads();
    float acc[CNY] = {};
    for (int n = 0; n < 256; ++n) {
        float v = g_X[(size_t)(n0 + n) * CNH + c];
#pragma unroll
        for (int j = 0; j < CNY; ++j) acc[j] = fmaf(v, ys[n * CNY + j], acc[j]);
    }
#pragma unroll
    for (int j = 0; j < CNY; ++j) g_apart[sp][c * CNY + j] = acc[j];
}

// ---------------- Cholesky + logdet + inverse ----------------
__global__ __launch_bounds__(64) void k_chol() {
    int g = blockIdx.x, tid = threadIdx.x;
    __shared__ float A[64][65];
    __shared__ float Yv[64][64];
    float rg = g_scal[0], t = g_scal[1];
    for (int i = 0; i < 64; ++i) {
        float m = 0.f;
#pragma unroll
        for (int sp = 0; sp < 4; ++sp) m += g_Mpart[sp][g * 4096 + i * 64 + tid];
        A[i][tid] = t * m + (i == tid ? rg : 0.f);
    }
    __syncthreads();
    for (int k = 0; k < 64; ++k) {
        float akk = A[k][k];
        float skk = sqrtf(akk);
        __syncthreads();
        if (tid == k) A[k][k] = skk;
        else if (tid > k) A[tid][k] = A[tid][k] / skk;
        __syncthreads();
        if (tid > k) {
            float lik = A[tid][k];
            for (int j = k + 1; j <= tid; ++j) A[tid][j] -= lik * A[j][k];
        }
        __syncthreads();
    }
    if (tid == 0) {
        float s = 0.f;
        for (int i = 0; i < 64; ++i) s += logf(A[i][i]);
        g_S[g] = 2.f * s;
    }
    const int c = tid;
    for (int i = 0; i < 64; ++i) {
        if (i < c) { Yv[i][c] = 0.f; continue; }
        float s = (i == c) ? 1.f : 0.f;
        for (int j = c; j < i; ++j) s -= A[i][j] * Yv[j][c];
        Yv[i][c] = s / A[i][i];
    }
    for (int i = 63; i >= 0; --i) {
        float s = Yv[i][c];
        for (int j = i + 1; j < 64; ++j) s -= A[j][i] * Yv[j][c];
        Yv[i][c] = s / A[i][i];
    }
    __syncthreads();
    for (int i = 0; i < 64; ++i) g_cov[g * 4096 + i * 64 + c] = Yv[i][c];
}

// ---------------- w0 = t*cov@a ; cw = cov@w0 ----------------
__global__ __launch_bounds__(256) void k_w0cw() {
    int g = blockIdx.x, tid = threadIdx.x;
    __shared__ float covs[64][65];
    __shared__ float as[64][17];
    __shared__ float w0s[64][17];
    for (int idx = tid; idx < 4096; idx += 256)
        covs[idx >> 6][idx & 63] = g_cov[g * 4096 + idx];
    for (int idx = tid; idx < 64 * CNY; idx += 256) {
        int i = idx >> 4, j = idx & 15;
        float s = 0.f;
#pragma unroll
        for (int sp = 0; sp < 8; ++sp) s += g_apart[sp][(g * 64 + i) * CNY + j];
        as[i][j] = s;
    }
    __syncthreads();
    float t = g_scal[1];
    int j = tid & 15, i0 = (tid >> 4) * 4;
#pragma unroll
    for (int ii = 0; ii < 4; ++ii) {
        float s = 0.f;
        for (int k = 0; k < 64; ++k) s = fmaf(covs[i0 + ii][k], as[k][j], s);
        w0s[i0 + ii][j] = t * s;
    }
    __syncthreads();
#pragma unroll
    for (int ii = 0; ii < 4; ++ii) {
        float s = 0.f;
        for (int k = 0; k < 64; ++k) s = fmaf(covs[i0 + ii][k], w0s[k][j], s);
        g_cw[(g * 64 + i0 + ii) * CNY + j] = s;
        g_w0[(g * 64 + i0 + ii) * CNY + j] = w0s[i0 + ii][j];
    }
}

// ---------------- softmax over groups -> p ----------------
__global__ __launch_bounds__(1024) void k_p() {
    int tid = threadIdx.x;
    int g = tid >> 4, j = tid & 15;
    float corr = 0.f;
    for (int i = 0; i < 64; ++i)
        corr = fmaf(g_w0[(g * 64 + i) * CNY + j], g_cw[(g * 64 + i) * CNY + j], corr);
    float t = g_scal[1];
    float lg = corr - t * g_ycss[j] - g_S[g];
    __shared__ float L[64][17];
    __shared__ float mx[16], sm[16];
    L[g][j] = lg;
    __syncthreads();
    if (tid < 16) {
        float m = -1e30f;
        for (int gg = 0; gg < 64; ++gg) m = fmaxf(m, L[gg][tid]);
        float s = 0.f;
        for (int gg = 0; gg < 64; ++gg) s += expf(L[gg][tid] - m);
        mx[tid] = m; sm[tid] = s;
    }
    __syncthreads();
    g_p[g * CNY + j] = expf(lg - mx[j]) / sm[j];
}

// ---------------- fold xmul into w and cov ----------------
__global__ void k_wprime() {
    int idx = blockIdx.x * 256 + threadIdx.x;
    int c = idx >> 4, j = idx & 15;
    g_w[idx] = g_w0[idx] * g_p[(c >> 6) * CNY + j] / g_xmul[c];
}
__global__ void k_covv() {
    int idx = blockIdx.x * 256 + threadIdx.x;
    int g = idx >> 12, i = (idx >> 6) & 63, j = idx & 63;
    g_covv[idx] = g_cov[idx] / (g_xmul[g * 64 + i] * g_xmul[g * 64 + j]);
}

// ---------------- fused predict: qy and qy_std ----------------
__global__ __launch_bounds__(128) void k_predict(float* __restrict__ out) {
    const int tid = threadIdx.x;
    const int r = tid >> 3, lane = tid & 7;
    const int row0 = blockIdx.x * 16;
    __shared__ float Xs[16][65];
    __shared__ float Cs[64][65];
    __shared__ float Ws[64][17];
    __shared__ float ps[16];
    float accy[CNY] = {};
    float v0 = 0.f, v1 = 0.f;
    for (int g = 0; g < CG; ++g) {
#pragma unroll
        for (int it = 0; it < 8; ++it) {
            int idx = tid + it * 128;
            Xs[idx >> 6][idx & 63] = g_XQ[(size_t)(row0 + (idx >> 6)) * CNH + g * 64 + (idx & 63)];
        }
#pragma unroll
        for (int it = 0; it < 32; ++it) {
            int idx = tid + it * 128;
            Cs[idx >> 6][idx & 63] = g_covv[g * 4096 + idx];
        }
#pragma unroll
        for (int it = 0; it < 8; ++it) {
            int idx = tid + it * 128;
            Ws[idx >> 4][idx & 15] = g_w[(g * 64 + (idx >> 4)) * CNY + (idx & 15)];
        }
        if (tid < 16) ps[tid] = g_p[g * CNY + tid];
        __syncthreads();
        float x[8];
#pragma unroll
        for (int ii = 0; ii < 8; ++ii) x[ii] = Xs[r][lane * 8 + ii];
#pragma unroll
        for (int ii = 0; ii < 8; ++ii)
#pragma unroll
            for (int j = 0; j < CNY; ++j)
                accy[j] = fmaf(x[ii], Ws[lane * 8 + ii][j], accy[j]);
        float s = 0.f;
        for (int jc = 0; jc < 64; ++jc) {
            float xj = Xs[r][jc];
            float q = 0.f;
#pragma unroll
            for (int ii = 0; ii < 8; ++ii) q = fmaf(Cs[lane * 8 + ii][jc], x[ii], q);
            s = fmaf(q, xj, s);
        }
        s += __shfl_xor_sync(0xffffffffu, s, 4);
        s += __shfl_xor_sync(0xffffffffu, s, 2);
        s += __shfl_xor_sync(0xffffffffu, s, 1);
        v0 = fmaf(s, ps[lane * 2 + 0], v0);
        v1 = fmaf(s, ps[lane * 2 + 1], v1);
        __syncthreads();
    }
#pragma unroll
    for (int j = 0; j < CNY; ++j) {
        accy[j] += __shfl_xor_sync(0xffffffffu, accy[j], 4);
        accy[j] += __shfl_xor_sync(0xffffffffu, accy[j], 2);
        accy[j] += __shfl_xor_sync(0xffffffffu, accy[j], 1);
    }
    const int row = row0 + r;
    const int j0 = lane * 2, j1 = j0 + 1;
    out[row * CNY + j0] = (accy[j0] + g_bmean[j0]) * g_ymul[j0];
    out[row * CNY + j1] = (accy[j1] + g_bmean[j1]) * g_ymul[j1];
    out[CN * CNY + row * CNY + j0] = sqrtf(fmaxf(v0, 0.f)) * g_ymul[j0];
    out[CN * CNY + row * CNY + j1] = sqrtf(fmaxf(v1, 0.f)) * g_ymul[j1];
}

// ---------------- launcher ----------------
extern "C" void kernel_launch(void* const* d_in, const int* in_sizes, int n_in,
                              void* d_out, int out_size) {
    const void* x  = d_in[0];
    const float* y = (const float*)d_in[1];
    const void* qx = d_in[2];
    const float* we = (const float*)d_in[3];
    const float* W1 = (const float*)d_in[4];
    const float* b1 = (const float*)d_in[5];
    const float* W2 = (const float*)d_in[6];
    const float* b2 = (const float*)d_in[7];
    const float* W3 = (const float*)d_in[8];
    const float* b3 = (const float*)d_in[9];
    const float* rp = (const float*)d_in[10];
    const float* tp = (const float*)d_in[11];
    float* out = (float*)d_out;

    float *pe, *ph1, *ph2, *pX, *pXQ;
    cudaGetSymbolAddress((void**)&pe,  g_e);
    cudaGetSymbolAddress((void**)&ph1, g_h1);
    cudaGetSymbolAddress((void**)&ph2, g_h2);
    cudaGetSymbolAddress((void**)&pX,  g_X);
    cudaGetSymbolAddress((void**)&pXQ, g_XQ);

    k_detect<<<1, 256>>>((const int*)x, in_sizes[0]);
    k_scal<<<1, 1>>>(rp, tp);
    k_ystats<<<16, 256>>>(y);

    const int gatherBlocks = (CN * (CNIN / 4) + 255) / 256;

    // embed train tokens -> g_X
    k_gather<<<gatherBlocks, 256>>>(x, (const float4*)we, (float4*)pe);
    k_gemm_tc<<<dim3(CH / 64, CN / 128), 256>>>(pe,  W1, b1, ph1, CN, CH,  CNIN, 1);
    k_gemm_tc<<<dim3(CH / 64, CN / 128), 256>>>(ph1, W2, b2, ph2, CN, CH,  CH,   1);
    k_gemm_tc<<<dim3(CNH / 64, CN / 128), 256>>>(ph2, W3, b3, pX,  CN, CNH, CH,   0);

    // embed query tokens -> g_XQ
    k_gather<<<gatherBlocks, 256>>>(qx, (const float4*)we, (float4*)pe);
    k_gemm_tc<<<dim3(CH / 64, CN / 128), 256>>>(pe,  W1, b1, ph1, CN, CH,  CNIN, 1);
    k_gemm_tc<<<dim3(CH / 64, CN / 128), 256>>>(ph1, W2, b2, ph2, CN, CH,  CH,   1);
    k_gemm_tc<<<dim3(CNH / 64, CN / 128), 256>>>(ph2, W3, b3, pXQ, CN, CNH, CH,   0);

    // ridge learn
    k_xstats<<<CNH / 256, 256>>>();
    k_xnorm<<<(CN * CNH) / 256, 256>>>();
    k_cov<<<dim3(CG, 4), 256>>>();
    k_apart<<<dim3(CNH / 256, 8), 256>>>();
    k_chol<<<CG, 64>>>();
    k_w0cw<<<CG, 256>>>();
    k_p<<<1, 1024>>>();
    k_wprime<<<(CNH * CNY) / 256, 256>>>();
    k_covv<<<(CG * 64 * 64) / 256, 256>>>();

    // fused predict (qy + qy_std)
    k_predict<<<CN / 16, 128>>>(out);
}

// round 4
// speedup vs baseline: 1.8664x; 1.4277x over previous
#include <cuda_runtime.h>
#include <cuda_bf16.h>
#include <math.h>
#include <stdint.h>

// ---------------- problem constants ----------------
#define CN   2048
#define CNY  16
#define CL   8
#define CD   768
#define CNIN 6144
#define CH   512
#define CNH  4096
#define CG   64
#define CV   50257

typedef __nv_bfloat16 bf16;

// ---------------- device scratch ----------------
__device__ __align__(16) bf16 g_eh[CN * CNIN];
__device__ __align__(16) bf16 g_el[CN * CNIN];
__device__ __align__(16) bf16 g_h1h[CN * CH];
__device__ __align__(16) bf16 g_h1l[CN * CH];
__device__ __align__(16) bf16 g_h2h[CN * CH];
__device__ __align__(16) bf16 g_h2l[CN * CH];
__device__ __align__(16) bf16 g_W1h[CH * CNIN];
__device__ __align__(16) bf16 g_W1l[CH * CNIN];
__device__ __align__(16) bf16 g_W2h[CH * CH];
__device__ __align__(16) bf16 g_W2l[CH * CH];
__device__ __align__(16) bf16 g_W3h[CNH * CH];
__device__ __align__(16) bf16 g_W3l[CNH * CH];
__device__ __align__(16) float g_X [CN * CNH];
__device__ __align__(16) float g_XQ[CN * CNH];
__device__ __align__(16) float g_xmul[CNH];
__device__ __align__(16) float g_Yc[CN * CNY];
__device__ __align__(16) float g_ymul[CNY];
__device__ __align__(16) float g_bmean[CNY];
__device__ __align__(16) float g_ycss[CNY];
__device__ __align__(16) float g_scal[2];
__device__ __align__(16) float g_Mpart[4][CG * 64 * 64];
__device__ __align__(16) float g_apart[8][CNH * CNY];
__device__ __align__(16) float g_cov [CG * 64 * 64];
__device__ __align__(16) float g_covv[CG * 64 * 64];
__device__ __align__(16) float g_S[CG];
__device__ __align__(16) float g_w0[CNH * CNY];
__device__ __align__(16) float g_cw[CNH * CNY];
__device__ __align__(16) float g_p [CG * CNY];
__device__ __align__(16) float g_w [CNH * CNY];
__device__ int g_tok64;

// ---------------- token dtype detection ----------------
__global__ void k_detect(const int* __restrict__ t, int n_elems) {
    __shared__ int nz;
    if (threadIdx.x == 0) nz = 0;
    __syncthreads();
    int local = 0;
    for (int i = 2 * threadIdx.x + 1; i < n_elems; i += 2 * 256)
        if (t[i] != 0) local = 1;
    if (local) atomicOr(&nz, 1);
    __syncthreads();
    if (threadIdx.x == 0) g_tok64 = (nz == 0) ? 1 : 0;
}

__global__ void k_scal(const float* __restrict__ rp, const float* __restrict__ tp) {
    g_scal[0] = expf(rp[0]) + 1e-8f;
    g_scal[1] = expf(tp[0]) + 1e-8f;
}

// ---------------- y stats ----------------
__global__ void k_ystats(const float* __restrict__ y) {
    int j = blockIdx.x, tid = threadIdx.x;
    __shared__ float red[256];
    __shared__ float sh_ym, sh_b;
    float s = 0.f, ss = 0.f;
    for (int n = tid; n < CN; n += 256) { float v = y[n * CNY + j]; s += v; ss += v * v; }
    red[tid] = s; __syncthreads();
    for (int st = 128; st; st >>= 1) { if (tid < st) red[tid] += red[tid + st]; __syncthreads(); }
    float S = red[0]; __syncthreads();
    red[tid] = ss; __syncthreads();
    for (int st = 128; st; st >>= 1) { if (tid < st) red[tid] += red[tid + st]; __syncthreads(); }
    float SS = red[0]; __syncthreads();
    if (tid == 0) {
        float var = (SS - S * S / (float)CN) / (float)(CN - 1);
        float ym = sqrtf(fmaxf(var, 0.f)) + 0.1f;
        float b = (S / (float)CN) / ym;
        sh_ym = ym; sh_b = b;
        g_ymul[j] = ym; g_bmean[j] = b;
    }
    __syncthreads();
    float ym = sh_ym, b = sh_b;
    float cs = 0.f;
    for (int n = tid; n < CN; n += 256) {
        float v = y[n * CNY + j] / ym - b;
        g_Yc[n * CNY + j] = v;
        cs += v * v;
    }
    red[tid] = cs; __syncthreads();
    for (int st = 128; st; st >>= 1) { if (tid < st) red[tid] += red[tid + st]; __syncthreads(); }
    if (tid == 0) g_ycss[j] = red[0];
}

// ---------------- split helpers ----------------
__device__ __forceinline__ void split2(float x, bf16& h, bf16& l) {
    h = __float2bfloat16_rn(x);
    l = __float2bfloat16_rn(x - __bfloat162float(h));
}

// ---------------- gather -> split bf16 ----------------
__global__ void k_gather(const void* __restrict__ tok, const float4* __restrict__ we4,
                         bf16* __restrict__ eh, bf16* __restrict__ el) {
    int idx = blockIdx.x * 256 + threadIdx.x;
    if (idx >= CN * (CNIN / 4)) return;
    int r = idx / (CNIN / 4), k4 = idx - r * (CNIN / 4);
    int l = k4 / (CD / 4), c4 = k4 - l * (CD / 4);
    long long t;
    if (g_tok64) t = ((const long long*)tok)[r * CL + l];
    else         t = (long long)((const int*)tok)[r * CL + l];
    if (t < 0) t = 0;
    if (t >= CV) t = CV - 1;
    float4 v = we4[(size_t)t * (CD / 4) + c4];
    bf16 h0,l0,h1,l1,h2,l2,h3,l3;
    split2(v.x,h0,l0); split2(v.y,h1,l1); split2(v.z,h2,l2); split2(v.w,h3,l3);
    ((__nv_bfloat162*)eh)[idx*2+0] = __nv_bfloat162(h0,h1);
    ((__nv_bfloat162*)eh)[idx*2+1] = __nv_bfloat162(h2,h3);
    ((__nv_bfloat162*)el)[idx*2+0] = __nv_bfloat162(l0,l1);
    ((__nv_bfloat162*)el)[idx*2+1] = __nv_bfloat162(l2,l3);
}

// ---------------- weight split ----------------
__global__ void k_split(const float4* __restrict__ w4, bf16* __restrict__ wh,
                        bf16* __restrict__ wl, int n4) {
    int idx = blockIdx.x * 256 + threadIdx.x;
    if (idx >= n4) return;
    float4 v = w4[idx];
    bf16 h0,l0,h1,l1,h2,l2,h3,l3;
    split2(v.x,h0,l0); split2(v.y,h1,l1); split2(v.z,h2,l2); split2(v.w,h3,l3);
    ((__nv_bfloat162*)wh)[idx*2+0] = __nv_bfloat162(h0,h1);
    ((__nv_bfloat162*)wh)[idx*2+1] = __nv_bfloat162(h2,h3);
    ((__nv_bfloat162*)wl)[idx*2+0] = __nv_bfloat162(l0,l1);
    ((__nv_bfloat162*)wl)[idx*2+1] = __nv_bfloat162(l2,l3);
}

// ---------------- split-bf16 tensor-core GEMM ----------------
// C[M,N] = A[M,K] @ B[N,K]^T via Ah*Bh + Ah*Bl + Al*Bh.
// Block 128x64, BK=32, 256 thr (8 warps 2x4), warp tile 64x16.
// cp.async double-buffered; XOR-swizzled 128B rows; ldmatrix fragments.
// mode 0: C fp32 + bias. mode 1: relu(C+bias) -> split bf16 (Ch, Cl).
#define ABYTES (128 * 128)
#define STAGEB (ABYTES + 64 * 128)

__global__ __launch_bounds__(256) void k_gemm_bf16(
    const bf16* __restrict__ Ah, const bf16* __restrict__ Al,
    const bf16* __restrict__ Bh, const bf16* __restrict__ Bl,
    const float* __restrict__ bias,
    float* __restrict__ Cf, bf16* __restrict__ Ch, bf16* __restrict__ Cl,
    int M, int Nn, int K, int mode)
{
    __shared__ __align__(16) char smem[2 * STAGEB];   // 48KB
    const uint32_t sbase = (uint32_t)__cvta_generic_to_shared(smem);
    const int tid = threadIdx.x;
    const int lane = tid & 31, wid = tid >> 5;
    const int warp_m = wid >> 2, warp_n = wid & 3;
    const int m0 = blockIdx.y * 128, n0 = blockIdx.x * 64;
    const int KT = K >> 5;

    float c[4][2][4];
#pragma unroll
    for (int i = 0; i < 4; ++i)
#pragma unroll
        for (int j = 0; j < 2; ++j)
#pragma unroll
            for (int r = 0; r < 4; ++r) c[i][j][r] = 0.f;

    // tile loader: 1536 x 16B cp.async
    auto load_tile = [&](int kt, int stage) {
        int k0 = kt << 5;
        uint32_t sb = sbase + stage * STAGEB;
#pragma unroll
        for (int i = 0; i < 6; ++i) {
            int id = tid + (i << 8);
            int isB = id >= 1024;
            int rid = isB ? id - 1024 : id;
            int r = rid >> 3, ck = rid & 7;
            const bf16* src;
            int grow;
            if (!isB) { grow = m0 + r; src = (ck < 4) ? Ah : Al; }
            else      { grow = n0 + r; src = (ck < 4) ? Bh : Bl; }
            const bf16* g = src + (size_t)grow * K + k0 + (ck & 3) * 8;
            uint32_t sa = sb + (isB ? ABYTES : 0) + r * 128 + ((ck ^ (r & 7)) << 4);
            asm volatile("cp.async.cg.shared.global [%0], [%1], 16;\n" :: "r"(sa), "l"(g));
        }
        asm volatile("cp.async.commit_group;\n");
    };

    load_tile(0, 0);

    for (int kt = 0; kt < KT; ++kt) {
        if (kt + 1 < KT) {
            load_tile(kt + 1, (kt + 1) & 1);
            asm volatile("cp.async.wait_group 1;\n");
        } else {
            asm volatile("cp.async.wait_group 0;\n");
        }
        __syncthreads();
        uint32_t sb = sbase + (kt & 1) * STAGEB;
#pragma unroll
        for (int s16 = 0; s16 < 2; ++s16) {
            uint32_t ahf[4][4], alf[4][4];
            uint32_t bhf[2][2], blf[2][2];
#pragma unroll
            for (int mt = 0; mt < 4; ++mt) {
                int r = warp_m * 64 + mt * 16 + (lane & 15);
                int cL = 2 * s16 + (lane >> 4);
                uint32_t a1 = sb + r * 128 + (((cL    ) ^ (r & 7)) << 4);
                uint32_t a2 = sb + r * 128 + (((cL + 4) ^ (r & 7)) << 4);
                asm volatile("ldmatrix.sync.aligned.m8n8.x4.shared.b16 {%0,%1,%2,%3}, [%4];"
                    : "=r"(ahf[mt][0]), "=r"(ahf[mt][1]), "=r"(ahf[mt][2]), "=r"(ahf[mt][3]) : "r"(a1));
                asm volatile("ldmatrix.sync.aligned.m8n8.x4.shared.b16 {%0,%1,%2,%3}, [%4];"
                    : "=r"(alf[mt][0]), "=r"(alf[mt][1]), "=r"(alf[mt][2]), "=r"(alf[mt][3]) : "r"(a2));
            }
#pragma unroll
            for (int nt = 0; nt < 2; ++nt) {
                int r = warp_n * 16 + nt * 8 + (lane & 7);
                int cL = 2 * s16 + ((lane >> 3) & 1);
                uint32_t a1 = sb + ABYTES + r * 128 + (((cL    ) ^ (r & 7)) << 4);
                uint32_t a2 = sb + ABYTES + r * 128 + (((cL + 4) ^ (r & 7)) << 4);
                asm volatile("ldmatrix.sync.aligned.m8n8.x2.shared.b16 {%0,%1}, [%2];"
                    : "=r"(bhf[nt][0]), "=r"(bhf[nt][1]) : "r"(a1));
                asm volatile("ldmatrix.sync.aligned.m8n8.x2.shared.b16 {%0,%1}, [%2];"
                    : "=r"(blf[nt][0]), "=r"(blf[nt][1]) : "r"(a2));
            }
#pragma unroll
            for (int mt = 0; mt < 4; ++mt)
#pragma unroll
                for (int nt = 0; nt < 2; ++nt) {
#define MMA(A0,A1,A2,A3,B0,B1) \
    asm volatile("mma.sync.aligned.m16n8k16.row.col.f32.bf16.bf16.f32 " \
        "{%0,%1,%2,%3}, {%4,%5,%6,%7}, {%8,%9}, {%0,%1,%2,%3};" \
        : "+f"(c[mt][nt][0]), "+f"(c[mt][nt][1]), "+f"(c[mt][nt][2]), "+f"(c[mt][nt][3]) \
        : "r"(A0), "r"(A1), "r"(A2), "r"(A3), "r"(B0), "r"(B1))
                    MMA(ahf[mt][0],ahf[mt][1],ahf[mt][2],ahf[mt][3], bhf[nt][0],bhf[nt][1]);
                    MMA(ahf[mt][0],ahf[mt][1],ahf[mt][2],ahf[mt][3], blf[nt][0],blf[nt][1]);
                    MMA(alf[mt][0],alf[mt][1],alf[mt][2],alf[mt][3], bhf[nt][0],bhf[nt][1]);
#undef MMA
                }
        }
        __syncthreads();
    }

    // epilogue
#pragma unroll
    for (int mt = 0; mt < 4; ++mt) {
        int row = m0 + warp_m * 64 + mt * 16 + (lane >> 2);
#pragma unroll
        for (int nt = 0; nt < 2; ++nt) {
            int col = n0 + warp_n * 16 + nt * 8 + 2 * (lane & 3);
            float b0 = bias[col], b1 = bias[col + 1];
            float v0 = c[mt][nt][0] + b0, v1 = c[mt][nt][1] + b1;
            float v2 = c[mt][nt][2] + b0, v3 = c[mt][nt][3] + b1;
            if (mode == 1) {
                v0 = fmaxf(v0, 0.f); v1 = fmaxf(v1, 0.f);
                v2 = fmaxf(v2, 0.f); v3 = fmaxf(v3, 0.f);
                bf16 h0,l0,h1,l1,h2,l2,h3,l3;
                split2(v0,h0,l0); split2(v1,h1,l1); split2(v2,h2,l2); split2(v3,h3,l3);
                *(__nv_bfloat162*)&Ch[(size_t)row * Nn + col] = __nv_bfloat162(h0, h1);
                *(__nv_bfloat162*)&Cl[(size_t)row * Nn + col] = __nv_bfloat162(l0, l1);
                *(__nv_bfloat162*)&Ch[(size_t)(row + 8) * Nn + col] = __nv_bfloat162(h2, h3);
                *(__nv_bfloat162*)&Cl[(size_t)(row + 8) * Nn + col] = __nv_bfloat162(l2, l3);
            } else {
                *(float2*)&Cf[(size_t)row * Nn + col] = make_float2(v0, v1);
                *(float2*)&Cf[(size_t)(row + 8) * Nn + col] = make_float2(v2, v3);
            }
        }
    }
}

// ---------------- per-column std of X -> xmul ----------------
__global__ void k_xstats() {
    int c = blockIdx.x * 256 + threadIdx.x;
    float s[8] = {}, ss[8] = {};
    for (int n = 0; n < CN; n += 8) {
#pragma unroll
        for (int u = 0; u < 8; ++u) {
            float v = g_X[(size_t)(n + u) * CNH + c];
            s[u] += v; ss[u] += v * v;
        }
    }
    double S = 0.0, SS = 0.0;
#pragma unroll
    for (int u = 0; u < 8; ++u) { S += (double)s[u]; SS += (double)ss[u]; }
    double var = (SS - S * S / (double)CN) / (double)(CN - 1);
    if (var < 0.0) var = 0.0;
    g_xmul[c] = (float)sqrt(var) + 0.1f;
}

__global__ void k_xnorm() {
    size_t idx = (size_t)blockIdx.x * 256 + threadIdx.x;
    g_X[idx] = g_X[idx] / g_xmul[idx & (CNH - 1)];
}

// ---------------- Gram partials ----------------
__global__ __launch_bounds__(256) void k_cov() {
    int g = blockIdx.x, sp = blockIdx.y, tid = threadIdx.x;
    __shared__ float tile[32][68];
    const int ti = (tid & 15) * 4, tj = (tid >> 4) * 4;
    float acc[4][4] = {};
    for (int n0 = sp * 512; n0 < sp * 512 + 512; n0 += 32) {
#pragma unroll
        for (int it = 0; it < 2; ++it) {
            int idx = tid + it * 256;
            int r = idx >> 4, c4 = idx & 15;
            float4 v = *(const float4*)&g_X[(size_t)(n0 + r) * CNH + g * 64 + c4 * 4];
            *(float4*)&tile[r][c4 * 4] = v;
        }
        __syncthreads();
#pragma unroll 4
        for (int r = 0; r < 32; ++r) {
            float xi[4], xj[4];
            *(float4*)xi = *(const float4*)&tile[r][ti];
            *(float4*)xj = *(const float4*)&tile[r][tj];
#pragma unroll
            for (int a = 0; a < 4; ++a)
#pragma unroll
                for (int b = 0; b < 4; ++b)
                    acc[a][b] = fmaf(xi[a], xj[b], acc[a][b]);
        }
        __syncthreads();
    }
    float* out = &g_Mpart[sp][g * 4096];
#pragma unroll
    for (int a = 0; a < 4; ++a)
#pragma unroll
        for (int b = 0; b < 4; ++b)
            out[(ti + a) * 64 + (tj + b)] = acc[a][b];
}

// ---------------- a partials ----------------
__global__ __launch_bounds__(256) void k_apart() {
    int c = blockIdx.x * 256 + threadIdx.x;
    int sp = blockIdx.y;
    int n0 = sp * 256;
    __shared__ float ys[256 * CNY];
    for (int i = threadIdx.x; i < 256 * CNY; i += 256) ys[i] = g_Yc[n0 * CNY + i];
    __syncthreads();
    float acc[CNY] = {};
    for (int n = 0; n < 256; ++n) {
        float v = g_X[(size_t)(n0 + n) * CNH + c];
#pragma unroll
        for (int j = 0; j < CNY; ++j) acc[j] = fmaf(v, ys[n * CNY + j], acc[j]);
    }
#pragma unroll
    for (int j = 0; j < CNY; ++j) g_apart[sp][c * CNY + j] = acc[j];
}

// ---------------- Cholesky + logdet + inverse ----------------
__global__ __launch_bounds__(64) void k_chol() {
    int g = blockIdx.x, tid = threadIdx.x;
    __shared__ float A[64][65];
    __shared__ float Yv[64][64];
    float rg = g_scal[0], t = g_scal[1];
    for (int i = 0; i < 64; ++i) {
        float m = 0.f;
#pragma unroll
        for (int sp = 0; sp < 4; ++sp) m += g_Mpart[sp][g * 4096 + i * 64 + tid];
        A[i][tid] = t * m + (i == tid ? rg : 0.f);
    }
    __syncthreads();
    for (int k = 0; k < 64; ++k) {
        float akk = A[k][k];
        float skk = sqrtf(akk);
        __syncthreads();
        if (tid == k) A[k][k] = skk;
        else if (tid > k) A[tid][k] = A[tid][k] / skk;
        __syncthreads();
        if (tid > k) {
            float lik = A[tid][k];
            for (int j = k + 1; j <= tid; ++j) A[tid][j] -= lik * A[j][k];
        }
        __syncthreads();
    }
    if (tid == 0) {
        float s = 0.f;
        for (int i = 0; i < 64; ++i) s += logf(A[i][i]);
        g_S[g] = 2.f * s;
    }
    const int c = tid;
    for (int i = 0; i < 64; ++i) {
        if (i < c) { Yv[i][c] = 0.f; continue; }
        float s = (i == c) ? 1.f : 0.f;
        for (int j = c; j < i; ++j) s -= A[i][j] * Yv[j][c];
        Yv[i][c] = s / A[i][i];
    }
    for (int i = 63; i >= 0; --i) {
        float s = Yv[i][c];
        for (int j = i + 1; j < 64; ++j) s -= A[j][i] * Yv[j][c];
        Yv[i][c] = s / A[i][i];
    }
    __syncthreads();
    for (int i = 0; i < 64; ++i) g_cov[g * 4096 + i * 64 + c] = Yv[i][c];
}

// ---------------- w0 = t*cov@a ; cw = cov@w0 ----------------
__global__ __launch_bounds__(256) void k_w0cw() {
    int g = blockIdx.x, tid = threadIdx.x;
    __shared__ float covs[64][65];
    __shared__ float as[64][17];
    __shared__ float w0s[64][17];
    for (int idx = tid; idx < 4096; idx += 256)
        covs[idx >> 6][idx & 63] = g_cov[g * 4096 + idx];
    for (int idx = tid; idx < 64 * CNY; idx += 256) {
        int i = idx >> 4, j = idx & 15;
        float s = 0.f;
#pragma unroll
        for (int sp = 0; sp < 8; ++sp) s += g_apart[sp][(g * 64 + i) * CNY + j];
        as[i][j] = s;
    }
    __syncthreads();
    float t = g_scal[1];
    int j = tid & 15, i0 = (tid >> 4) * 4;
#pragma unroll
    for (int ii = 0; ii < 4; ++ii) {
        float s = 0.f;
        for (int k = 0; k < 64; ++k) s = fmaf(covs[i0 + ii][k], as[k][j], s);
        w0s[i0 + ii][j] = t * s;
    }
    __syncthreads();
#pragma unroll
    for (int ii = 0; ii < 4; ++ii) {
        float s = 0.f;
        for (int k = 0; k < 64; ++k) s = fmaf(covs[i0 + ii][k], w0s[k][j], s);
        g_cw[(g * 64 + i0 + ii) * CNY + j] = s;
        g_w0[(g * 64 + i0 + ii) * CNY + j] = w0s[i0 + ii][j];
    }
}

// ---------------- softmax over groups -> p ----------------
__global__ __launch_bounds__(1024) void k_p() {
    int tid = threadIdx.x;
    int g = tid >> 4, j = tid & 15;
    float corr = 0.f;
    for (int i = 0; i < 64; ++i)
        corr = fmaf(g_w0[(g * 64 + i) * CNY + j], g_cw[(g * 64 + i) * CNY + j], corr);
    float t = g_scal[1];
    float lg = corr - t * g_ycss[j] - g_S[g];
    __shared__ float L[64][17];
    __shared__ float mx[16], sm[16];
    L[g][j] = lg;
    __syncthreads();
    if (tid < 16) {
        float m = -1e30f;
        for (int gg = 0; gg < 64; ++gg) m = fmaxf(m, L[gg][tid]);
        float s = 0.f;
        for (int gg = 0; gg < 64; ++gg) s += expf(L[gg][tid] - m);
        mx[tid] = m; sm[tid] = s;
    }
    __syncthreads();
    g_p[g * CNY + j] = expf(lg - mx[j]) / sm[j];
}

// ---------------- fold xmul into w and cov ----------------
__global__ void k_wprime() {
    int idx = blockIdx.x * 256 + threadIdx.x;
    int c = idx >> 4, j = idx & 15;
    g_w[idx] = g_w0[idx] * g_p[(c >> 6) * CNY + j] / g_xmul[c];
}
__global__ void k_covv() {
    int idx = blockIdx.x * 256 + threadIdx.x;
    int g = idx >> 12, i = (idx >> 6) & 63, j = idx & 63;
    g_covv[idx] = g_cov[idx] / (g_xmul[g * 64 + i] * g_xmul[g * 64 + j]);
}

// ---------------- fused predict: qy and qy_std ----------------
__global__ __launch_bounds__(128) void k_predict(float* __restrict__ out) {
    const int tid = threadIdx.x;
    const int r = tid >> 3, lane = tid & 7;
    const int row0 = blockIdx.x * 16;
    __shared__ float Xs[16][65];
    __shared__ float Cs[64][65];
    __shared__ float Ws[64][17];
    __shared__ float ps[16];
    float accy[CNY] = {};
    float v0 = 0.f, v1 = 0.f;
    for (int g = 0; g < CG; ++g) {
#pragma unroll
        for (int it = 0; it < 8; ++it) {
            int idx = tid + it * 128;
            Xs[idx >> 6][idx & 63] = g_XQ[(size_t)(row0 + (idx >> 6)) * CNH + g * 64 + (idx & 63)];
        }
#pragma unroll
        for (int it = 0; it < 32; ++it) {
            int idx = tid + it * 128;
            Cs[idx >> 6][idx & 63] = g_covv[g * 4096 + idx];
        }
#pragma unroll
        for (int it = 0; it < 8; ++it) {
            int idx = tid + it * 128;
            Ws[idx >> 4][idx & 15] = g_w[(g * 64 + (idx >> 4)) * CNY + (idx & 15)];
        }
        if (tid < 16) ps[tid] = g_p[g * CNY + tid];
        __syncthreads();
        float x[8];
#pragma unroll
        for (int ii = 0; ii < 8; ++ii) x[ii] = Xs[r][lane * 8 + ii];
#pragma unroll
        for (int ii = 0; ii < 8; ++ii)
#pragma unroll
            for (int j = 0; j < CNY; ++j)
                accy[j] = fmaf(x[ii], Ws[lane * 8 + ii][j], accy[j]);
        float s = 0.f;
        for (int jc = 0; jc < 64; ++jc) {
            float xj = Xs[r][jc];
            float q = 0.f;
#pragma unroll
            for (int ii = 0; ii < 8; ++ii) q = fmaf(Cs[lane * 8 + ii][jc], x[ii], q);
            s = fmaf(q, xj, s);
        }
        s += __shfl_xor_sync(0xffffffffu, s, 4);
        s += __shfl_xor_sync(0xffffffffu, s, 2);
        s += __shfl_xor_sync(0xffffffffu, s, 1);
        v0 = fmaf(s, ps[lane * 2 + 0], v0);
        v1 = fmaf(s, ps[lane * 2 + 1], v1);
        __syncthreads();
    }
#pragma unroll
    for (int j = 0; j < CNY; ++j) {
        accy[j] += __shfl_xor_sync(0xffffffffu, accy[j], 4);
        accy[j] += __shfl_xor_sync(0xffffffffu, accy[j], 2);
        accy[j] += __shfl_xor_sync(0xffffffffu, accy[j], 1);
    }
    const int row = row0 + r;
    const int j0 = lane * 2, j1 = j0 + 1;
    out[row * CNY + j0] = (accy[j0] + g_bmean[j0]) * g_ymul[j0];
    out[row * CNY + j1] = (accy[j1] + g_bmean[j1]) * g_ymul[j1];
    out[CN * CNY + row * CNY + j0] = sqrtf(fmaxf(v0, 0.f)) * g_ymul[j0];
    out[CN * CNY + row * CNY + j1] = sqrtf(fmaxf(v1, 0.f)) * g_ymul[j1];
}

// ---------------- launcher ----------------
extern "C" void kernel_launch(void* const* d_in, const int* in_sizes, int n_in,
                              void* d_out, int out_size) {
    const void* x  = d_in[0];
    const float* y = (const float*)d_in[1];
    const void* qx = d_in[2];
    const float* we = (const float*)d_in[3];
    const float* W1 = (const float*)d_in[4];
    const float* b1 = (const float*)d_in[5];
    const float* W2 = (const float*)d_in[6];
    const float* b2 = (const float*)d_in[7];
    const float* W3 = (const float*)d_in[8];
    const float* b3 = (const float*)d_in[9];
    const float* rp = (const float*)d_in[10];
    const float* tp = (const float*)d_in[11];
    float* out = (float*)d_out;

    bf16 *peh, *pel, *ph1h, *ph1l, *ph2h, *ph2l;
    bf16 *pW1h, *pW1l, *pW2h, *pW2l, *pW3h, *pW3l;
    float *pX, *pXQ;
    cudaGetSymbolAddress((void**)&peh,  g_eh);
    cudaGetSymbolAddress((void**)&pel,  g_el);
    cudaGetSymbolAddress((void**)&ph1h, g_h1h);
    cudaGetSymbolAddress((void**)&ph1l, g_h1l);
    cudaGetSymbolAddress((void**)&ph2h, g_h2h);
    cudaGetSymbolAddress((void**)&ph2l, g_h2l);
    cudaGetSymbolAddress((void**)&pW1h, g_W1h);
    cudaGetSymbolAddress((void**)&pW1l, g_W1l);
    cudaGetSymbolAddress((void**)&pW2h, g_W2h);
    cudaGetSymbolAddress((void**)&pW2l, g_W2l);
    cudaGetSymbolAddress((void**)&pW3h, g_W3h);
    cudaGetSymbolAddress((void**)&pW3l, g_W3l);
    cudaGetSymbolAddress((void**)&pX,  g_X);
    cudaGetSymbolAddress((void**)&pXQ, g_XQ);

    k_detect<<<1, 256>>>((const int*)x, in_sizes[0]);
    k_scal<<<1, 1>>>(rp, tp);
    k_ystats<<<16, 256>>>(y);

    // split weights
    k_split<<<(CH * CNIN / 4 + 255) / 256, 256>>>((const float4*)W1, pW1h, pW1l, CH * CNIN / 4);
    k_split<<<(CH * CH   / 4 + 255) / 256, 256>>>((const float4*)W2, pW2h, pW2l, CH * CH / 4);
    k_split<<<(CNH * CH  / 4 + 255) / 256, 256>>>((const float4*)W3, pW3h, pW3l, CNH * CH / 4);

    const int gatherBlocks = (CN * (CNIN / 4) + 255) / 256;

    // embed train tokens -> g_X
    k_gather<<<gatherBlocks, 256>>>(x, (const float4*)we, peh, pel);
    k_gemm_bf16<<<dim3(CH / 64, CN / 128), 256>>>(peh, pel, pW1h, pW1l, b1, nullptr, ph1h, ph1l, CN, CH, CNIN, 1);
    k_gemm_bf16<<<dim3(CH / 64, CN / 128), 256>>>(ph1h, ph1l, pW2h, pW2l, b2, nullptr, ph2h, ph2l, CN, CH, CH, 1);
    k_gemm_bf16<<<dim3(CNH / 64, CN / 128), 256>>>(ph2h, ph2l, pW3h, pW3l, b3, pX, nullptr, nullptr, CN, CNH, CH, 0);

    // embed query tokens -> g_XQ
    k_gather<<<gatherBlocks, 256>>>(qx, (const float4*)we, peh, pel);
    k_gemm_bf16<<<dim3(CH / 64, CN / 128), 256>>>(peh, pel, pW1h, pW1l, b1, nullptr, ph1h, ph1l, CN, CH, CNIN, 1);
    k_gemm_bf16<<<dim3(CH / 64, CN / 128), 256>>>(ph1h, ph1l, pW2h, pW2l, b2, nullptr, ph2h, ph2l, CN, CH, CH, 1);
    k_gemm_bf16<<<dim3(CNH / 64, CN / 128), 256>>>(ph2h, ph2l, pW3h, pW3l, b3, pXQ, nullptr, nullptr, CN, CNH, CH, 0);

    // ridge learn
    k_xstats<<<CNH / 256, 256>>>();
    k_xnorm<<<(CN * CNH) / 256, 256>>>();
    k_cov<<<dim3(CG, 4), 256>>>();
    k_apart<<<dim3(CNH / 256, 8), 256>>>();
    k_chol<<<CG, 64>>>();
    k_w0cw<<<CG, 256>>>();
    k_p<<<1, 1024>>>();
    k_wprime<<<(CNH * CNY) / 256, 256>>>();
    k_covv<<<(CG * 64 * 64) / 256, 256>>>();

    // fused predict (qy + qy_std)
    k_predict<<<CN / 16, 128>>>(out);
}

// round 5
// speedup vs baseline: 2.0761x; 1.1124x over previous
#include <cuda_runtime.h>
#include <cuda_bf16.h>
#include <math.h>
#include <stdint.h>

// ---------------- problem constants ----------------
#define CN   2048
#define CN2  4096          // merged train+query batch
#define CNY  16
#define CL   8
#define CD   768
#define CNIN 6144
#define CH   512
#define CNH  4096
#define CG   64
#define CV   50257

typedef __nv_bfloat16 bf16;

// ---------------- device scratch ----------------
__device__ __align__(16) bf16 g_eh[CN2 * CNIN];
__device__ __align__(16) bf16 g_el[CN2 * CNIN];
__device__ __align__(16) bf16 g_h1h[CN2 * CH];
__device__ __align__(16) bf16 g_h1l[CN2 * CH];
__device__ __align__(16) bf16 g_h2h[CN2 * CH];
__device__ __align__(16) bf16 g_h2l[CN2 * CH];
__device__ __align__(16) bf16 g_W1h[CH * CNIN];
__device__ __align__(16) bf16 g_W1l[CH * CNIN];
__device__ __align__(16) bf16 g_W2h[CH * CH];
__device__ __align__(16) bf16 g_W2l[CH * CH];
__device__ __align__(16) bf16 g_W3h[CNH * CH];
__device__ __align__(16) bf16 g_W3l[CNH * CH];
__device__ __align__(16) float g_X [CN2 * CNH];     // rows 0..2047 train, 2048.. query
__device__ __align__(16) float g_xmul[CNH];
__device__ __align__(16) float g_Yc[CN * CNY];
__device__ __align__(16) float g_ymul[CNY];
__device__ __align__(16) float g_bmean[CNY];
__device__ __align__(16) float g_ycss[CNY];
__device__ __align__(16) float g_scal[2];
__device__ __align__(16) float g_Mpart[4][CG * 64 * 64];
__device__ __align__(16) float g_apart[8][CNH * CNY];
__device__ __align__(16) float g_cov [CG * 64 * 64];
__device__ __align__(16) float g_covv[CG * 64 * 64];
__device__ __align__(16) float g_S[CG];
__device__ __align__(16) float g_w0[CNH * CNY];
__device__ __align__(16) float g_cw[CNH * CNY];
__device__ __align__(16) float g_p [CG * CNY];
__device__ __align__(16) float g_w [CNH * CNY];
__device__ int g_tok64;

// ---------------- token dtype detection ----------------
__global__ void k_detect(const int* __restrict__ t, int n_elems) {
    __shared__ int nz;
    if (threadIdx.x == 0) nz = 0;
    __syncthreads();
    int local = 0;
    for (int i = 2 * threadIdx.x + 1; i < n_elems; i += 2 * 256)
        if (t[i] != 0) local = 1;
    if (local) atomicOr(&nz, 1);
    __syncthreads();
    if (threadIdx.x == 0) g_tok64 = (nz == 0) ? 1 : 0;
}

__global__ void k_scal(const float* __restrict__ rp, const float* __restrict__ tp) {
    g_scal[0] = expf(rp[0]) + 1e-8f;
    g_scal[1] = expf(tp[0]) + 1e-8f;
}

// ---------------- y stats ----------------
__global__ void k_ystats(const float* __restrict__ y) {
    int j = blockIdx.x, tid = threadIdx.x;
    __shared__ float red[256];
    __shared__ float sh_ym, sh_b;
    float s = 0.f, ss = 0.f;
    for (int n = tid; n < CN; n += 256) { float v = y[n * CNY + j]; s += v; ss += v * v; }
    red[tid] = s; __syncthreads();
    for (int st = 128; st; st >>= 1) { if (tid < st) red[tid] += red[tid + st]; __syncthreads(); }
    float S = red[0]; __syncthreads();
    red[tid] = ss; __syncthreads();
    for (int st = 128; st; st >>= 1) { if (tid < st) red[tid] += red[tid + st]; __syncthreads(); }
    float SS = red[0]; __syncthreads();
    if (tid == 0) {
        float var = (SS - S * S / (float)CN) / (float)(CN - 1);
        float ym = sqrtf(fmaxf(var, 0.f)) + 0.1f;
        float b = (S / (float)CN) / ym;
        sh_ym = ym; sh_b = b;
        g_ymul[j] = ym; g_bmean[j] = b;
    }
    __syncthreads();
    float ym = sh_ym, b = sh_b;
    float cs = 0.f;
    for (int n = tid; n < CN; n += 256) {
        float v = y[n * CNY + j] / ym - b;
        g_Yc[n * CNY + j] = v;
        cs += v * v;
    }
    red[tid] = cs; __syncthreads();
    for (int st = 128; st; st >>= 1) { if (tid < st) red[tid] += red[tid + st]; __syncthreads(); }
    if (tid == 0) g_ycss[j] = red[0];
}

// ---------------- split helpers ----------------
__device__ __forceinline__ void split2(float x, bf16& h, bf16& l) {
    h = __float2bfloat16_rn(x);
    l = __float2bfloat16_rn(x - __bfloat162float(h));
}

// ---------------- merged gather (train rows 0..2047, query 2048..4095) ----------
__global__ void k_gather(const void* __restrict__ tokx, const void* __restrict__ tokq,
                         const float4* __restrict__ we4,
                         bf16* __restrict__ eh, bf16* __restrict__ el) {
    int idx = blockIdx.x * 256 + threadIdx.x;
    if (idx >= CN2 * (CNIN / 4)) return;
    int r = idx / (CNIN / 4), k4 = idx - r * (CNIN / 4);
    int l = k4 / (CD / 4), c4 = k4 - l * (CD / 4);
    const void* tok = (r < CN) ? tokx : tokq;
    int rr = (r < CN) ? r : r - CN;
    long long t;
    if (g_tok64) t = ((const long long*)tok)[rr * CL + l];
    else         t = (long long)((const int*)tok)[rr * CL + l];
    if (t < 0) t = 0;
    if (t >= CV) t = CV - 1;
    float4 v = we4[(size_t)t * (CD / 4) + c4];
    bf16 h0,l0,h1,l1,h2,l2,h3,l3;
    split2(v.x,h0,l0); split2(v.y,h1,l1); split2(v.z,h2,l2); split2(v.w,h3,l3);
    ((__nv_bfloat162*)eh)[idx*2+0] = __nv_bfloat162(h0,h1);
    ((__nv_bfloat162*)eh)[idx*2+1] = __nv_bfloat162(h2,h3);
    ((__nv_bfloat162*)el)[idx*2+0] = __nv_bfloat162(l0,l1);
    ((__nv_bfloat162*)el)[idx*2+1] = __nv_bfloat162(l2,l3);
}

// ---------------- weight split ----------------
__global__ void k_split(const float4* __restrict__ w4, bf16* __restrict__ wh,
                        bf16* __restrict__ wl, int n4) {
    int idx = blockIdx.x * 256 + threadIdx.x;
    if (idx >= n4) return;
    float4 v = w4[idx];
    bf16 h0,l0,h1,l1,h2,l2,h3,l3;
    split2(v.x,h0,l0); split2(v.y,h1,l1); split2(v.z,h2,l2); split2(v.w,h3,l3);
    ((__nv_bfloat162*)wh)[idx*2+0] = __nv_bfloat162(h0,h1);
    ((__nv_bfloat162*)wh)[idx*2+1] = __nv_bfloat162(h2,h3);
    ((__nv_bfloat162*)wl)[idx*2+0] = __nv_bfloat162(l0,l1);
    ((__nv_bfloat162*)wl)[idx*2+1] = __nv_bfloat162(l2,l3);
}

// ---------------- split-bf16 tensor-core GEMM ----------------
// C[M,N] = A[M,K] @ B[N,K]^T via Ah*Bh + Ah*Bl + Al*Bh.
// Block 128x128, BK=16, 256 thr (warps 2m x 4n), warp tile 64x32.
// 4-stage cp.async ring (16KB/stage, 64KB dynamic smem), one sync per tile.
// Row layout: 64B/row = 4x16B chunks {hi0,hi1,lo0,lo1}; phys chunk = ck ^ ((r>>1)&3).
#define GSTAGE 16384
#define GBOFF  8192

__global__ __launch_bounds__(256) void k_gemm_bf16(
    const bf16* __restrict__ Ah, const bf16* __restrict__ Al,
    const bf16* __restrict__ Bh, const bf16* __restrict__ Bl,
    const float* __restrict__ bias,
    float* __restrict__ Cf, bf16* __restrict__ Ch, bf16* __restrict__ Cl,
    int M, int Nn, int K, int mode)
{
    extern __shared__ __align__(16) char smem[];
    const uint32_t sbase = (uint32_t)__cvta_generic_to_shared(smem);
    const int tid = threadIdx.x;
    const int lane = tid & 31, wid = tid >> 5;
    const int warp_m = wid >> 2, warp_n = wid & 3;
    const int m0 = blockIdx.y * 128, n0 = blockIdx.x * 128;
    const int KT = K >> 4;

    float c[4][4][4];
#pragma unroll
    for (int i = 0; i < 4; ++i)
#pragma unroll
        for (int j = 0; j < 4; ++j)
#pragma unroll
            for (int r = 0; r < 4; ++r) c[i][j][r] = 0.f;

    auto load_tile = [&](int kt, int stage) {
        int k0 = kt << 4;
        uint32_t sb = sbase + stage * GSTAGE;
#pragma unroll
        for (int i = 0; i < 4; ++i) {
            int id = tid + (i << 8);
            int isB = id >= 512;
            int rid = id & 511;
            int r = rid >> 2, ck = rid & 3;
            const bf16* src = (ck < 2) ? (isB ? Bh : Ah) : (isB ? Bl : Al);
            int grow = (isB ? n0 : m0) + r;
            const bf16* g = src + (size_t)grow * K + k0 + (ck & 1) * 8;
            uint32_t sa = sb + (isB ? GBOFF : 0) + r * 64 + ((ck ^ ((r >> 1) & 3)) << 4);
            asm volatile("cp.async.cg.shared.global [%0], [%1], 16;\n" :: "r"(sa), "l"(g));
        }
        asm volatile("cp.async.commit_group;\n");
    };

    if (KT > 0) load_tile(0, 0);
    if (KT > 1) load_tile(1, 1);

    for (int kt = 0; kt < KT; ++kt) {
        if (kt + 2 < KT) {
            load_tile(kt + 2, (kt + 2) & 3);
            asm volatile("cp.async.wait_group 2;\n");
        } else if (kt + 1 < KT) {
            asm volatile("cp.async.wait_group 1;\n");
        } else {
            asm volatile("cp.async.wait_group 0;\n");
        }
        __syncthreads();
        uint32_t sb = sbase + (kt & 3) * GSTAGE;

        uint32_t ahf[4][4], alf[4][4], bhf[4][2], blf[4][2];
#pragma unroll
        for (int mt = 0; mt < 4; ++mt) {
            int r = warp_m * 64 + mt * 16 + (lane & 15);
            int sw = (r >> 1) & 3;
            int ckh = lane >> 4;
            uint32_t a1 = sb + r * 64 + ((ckh ^ sw) << 4);
            uint32_t a2 = sb + r * 64 + (((ckh + 2) ^ sw) << 4);
            asm volatile("ldmatrix.sync.aligned.m8n8.x4.shared.b16 {%0,%1,%2,%3}, [%4];"
                : "=r"(ahf[mt][0]), "=r"(ahf[mt][1]), "=r"(ahf[mt][2]), "=r"(ahf[mt][3]) : "r"(a1));
            asm volatile("ldmatrix.sync.aligned.m8n8.x4.shared.b16 {%0,%1,%2,%3}, [%4];"
                : "=r"(alf[mt][0]), "=r"(alf[mt][1]), "=r"(alf[mt][2]), "=r"(alf[mt][3]) : "r"(a2));
        }
#pragma unroll
        for (int nt = 0; nt < 4; ++nt) {
            int r = warp_n * 32 + nt * 8 + (lane & 7);
            int sw = (r >> 1) & 3;
            int ckb = (lane >> 3) & 1;
            uint32_t b1 = sb + GBOFF + r * 64 + ((ckb ^ sw) << 4);
            uint32_t b2 = sb + GBOFF + r * 64 + (((ckb + 2) ^ sw) << 4);
            asm volatile("ldmatrix.sync.aligned.m8n8.x2.shared.b16 {%0,%1}, [%2];"
                : "=r"(bhf[nt][0]), "=r"(bhf[nt][1]) : "r"(b1));
            asm volatile("ldmatrix.sync.aligned.m8n8.x2.shared.b16 {%0,%1}, [%2];"
                : "=r"(blf[nt][0]), "=r"(blf[nt][1]) : "r"(b2));
        }
#pragma unroll
        for (int mt = 0; mt < 4; ++mt)
#pragma unroll
            for (int nt = 0; nt < 4; ++nt) {
#define MMA(A0,A1,A2,A3,B0,B1) \
    asm volatile("mma.sync.aligned.m16n8k16.row.col.f32.bf16.bf16.f32 " \
        "{%0,%1,%2,%3}, {%4,%5,%6,%7}, {%8,%9}, {%0,%1,%2,%3};" \
        : "+f"(c[mt][nt][0]), "+f"(c[mt][nt][1]), "+f"(c[mt][nt][2]), "+f"(c[mt][nt][3]) \
        : "r"(A0), "r"(A1), "r"(A2), "r"(A3), "r"(B0), "r"(B1))
                MMA(ahf[mt][0],ahf[mt][1],ahf[mt][2],ahf[mt][3], bhf[nt][0],bhf[nt][1]);
                MMA(ahf[mt][0],ahf[mt][1],ahf[mt][2],ahf[mt][3], blf[nt][0],blf[nt][1]);
                MMA(alf[mt][0],alf[mt][1],alf[mt][2],alf[mt][3], bhf[nt][0],bhf[nt][1]);
#undef MMA
            }
    }

    // epilogue
#pragma unroll
    for (int mt = 0; mt < 4; ++mt) {
        int row = m0 + warp_m * 64 + mt * 16 + (lane >> 2);
#pragma unroll
        for (int nt = 0; nt < 4; ++nt) {
            int col = n0 + warp_n * 32 + nt * 8 + 2 * (lane & 3);
            float b0 = bias[col], b1 = bias[col + 1];
            float v0 = c[mt][nt][0] + b0, v1 = c[mt][nt][1] + b1;
            float v2 = c[mt][nt][2] + b0, v3 = c[mt][nt][3] + b1;
            if (mode == 1) {
                v0 = fmaxf(v0, 0.f); v1 = fmaxf(v1, 0.f);
                v2 = fmaxf(v2, 0.f); v3 = fmaxf(v3, 0.f);
                bf16 h0,l0,h1,l1,h2,l2,h3,l3;
                split2(v0,h0,l0); split2(v1,h1,l1); split2(v2,h2,l2); split2(v3,h3,l3);
                *(__nv_bfloat162*)&Ch[(size_t)row * Nn + col] = __nv_bfloat162(h0, h1);
                *(__nv_bfloat162*)&Cl[(size_t)row * Nn + col] = __nv_bfloat162(l0, l1);
                *(__nv_bfloat162*)&Ch[(size_t)(row + 8) * Nn + col] = __nv_bfloat162(h2, h3);
                *(__nv_bfloat162*)&Cl[(size_t)(row + 8) * Nn + col] = __nv_bfloat162(l2, l3);
            } else {
                *(float2*)&Cf[(size_t)row * Nn + col] = make_float2(v0, v1);
                *(float2*)&Cf[(size_t)(row + 8) * Nn + col] = make_float2(v2, v3);
            }
        }
    }
}

// ---------------- per-column std of X (train rows) -> xmul ----------------
__global__ void k_xstats() {
    int c = blockIdx.x * 256 + threadIdx.x;
    float s[8] = {}, ss[8] = {};
    for (int n = 0; n < CN; n += 8) {
#pragma unroll
        for (int u = 0; u < 8; ++u) {
            float v = g_X[(size_t)(n + u) * CNH + c];
            s[u] += v; ss[u] += v * v;
        }
    }
    double S = 0.0, SS = 0.0;
#pragma unroll
    for (int u = 0; u < 8; ++u) { S += (double)s[u]; SS += (double)ss[u]; }
    double var = (SS - S * S / (double)CN) / (double)(CN - 1);
    if (var < 0.0) var = 0.0;
    g_xmul[c] = (float)sqrt(var) + 0.1f;
}

// ---------------- Gram partials (xmul folded on load) ----------------
__global__ __launch_bounds__(256) void k_cov() {
    int g = blockIdx.x, sp = blockIdx.y, tid = threadIdx.x;
    __shared__ float tile[32][68];
    __shared__ float xminv[64];
    if (tid < 64) xminv[tid] = 1.0f / g_xmul[g * 64 + tid];
    __syncthreads();
    const int ti = (tid & 15) * 4, tj = (tid >> 4) * 4;
    float acc[4][4] = {};
    for (int n0 = sp * 512; n0 < sp * 512 + 512; n0 += 32) {
#pragma unroll
        for (int it = 0; it < 2; ++it) {
            int idx = tid + it * 256;
            int r = idx >> 4, c4 = idx & 15;
            float4 v = *(const float4*)&g_X[(size_t)(n0 + r) * CNH + g * 64 + c4 * 4];
            v.x *= xminv[c4*4+0]; v.y *= xminv[c4*4+1];
            v.z *= xminv[c4*4+2]; v.w *= xminv[c4*4+3];
            *(float4*)&tile[r][c4 * 4] = v;
        }
        __syncthreads();
#pragma unroll 4
        for (int r = 0; r < 32; ++r) {
            float xi[4], xj[4];
            *(float4*)xi = *(const float4*)&tile[r][ti];
            *(float4*)xj = *(const float4*)&tile[r][tj];
#pragma unroll
            for (int a = 0; a < 4; ++a)
#pragma unroll
                for (int b = 0; b < 4; ++b)
                    acc[a][b] = fmaf(xi[a], xj[b], acc[a][b]);
        }
        __syncthreads();
    }
    float* out = &g_Mpart[sp][g * 4096];
#pragma unroll
    for (int a = 0; a < 4; ++a)
#pragma unroll
        for (int b = 0; b < 4; ++b)
            out[(ti + a) * 64 + (tj + b)] = acc[a][b];
}

// ---------------- a partials (xmul folded) ----------------
__global__ __launch_bounds__(256) void k_apart() {
    int c = blockIdx.x * 256 + threadIdx.x;
    int sp = blockIdx.y;
    int n0 = sp * 256;
    __shared__ float ys[256 * CNY];
    for (int i = threadIdx.x; i < 256 * CNY; i += 256) ys[i] = g_Yc[n0 * CNY + i];
    __syncthreads();
    float xinv = 1.0f / g_xmul[c];
    float acc[CNY] = {};
    for (int n = 0; n < 256; ++n) {
        float v = g_X[(size_t)(n0 + n) * CNH + c] * xinv;
#pragma unroll
        for (int j = 0; j < CNY; ++j) acc[j] = fmaf(v, ys[n * CNY + j], acc[j]);
    }
#pragma unroll
    for (int j = 0; j < CNY; ++j) g_apart[sp][c * CNY + j] = acc[j];
}

// ---------------- Cholesky + logdet + inverse ----------------
__global__ __launch_bounds__(64) void k_chol() {
    int g = blockIdx.x, tid = threadIdx.x;
    __shared__ float A[64][65];
    __shared__ float Yv[64][64];
    float rg = g_scal[0], t = g_scal[1];
    for (int i = 0; i < 64; ++i) {
        float m = 0.f;
#pragma unroll
        for (int sp = 0; sp < 4; ++sp) m += g_Mpart[sp][g * 4096 + i * 64 + tid];
        A[i][tid] = t * m + (i == tid ? rg : 0.f);
    }
    __syncthreads();
    for (int k = 0; k < 64; ++k) {
        float akk = A[k][k];
        float skk = sqrtf(akk);
        __syncthreads();
        if (tid == k) A[k][k] = skk;
        else if (tid > k) A[tid][k] = A[tid][k] / skk;
        __syncthreads();
        if (tid > k) {
            float lik = A[tid][k];
            for (int j = k + 1; j <= tid; ++j) A[tid][j] -= lik * A[j][k];
        }
        __syncthreads();
    }
    if (tid == 0) {
        float s = 0.f;
        for (int i = 0; i < 64; ++i) s += logf(A[i][i]);
        g_S[g] = 2.f * s;
    }
    const int c = tid;
    for (int i = 0; i < 64; ++i) {
        if (i < c) { Yv[i][c] = 0.f; continue; }
        float s = (i == c) ? 1.f : 0.f;
        for (int j = c; j < i; ++j) s -= A[i][j] * Yv[j][c];
        Yv[i][c] = s / A[i][i];
    }
    for (int i = 63; i >= 0; --i) {
        float s = Yv[i][c];
        for (int j = i + 1; j < 64; ++j) s -= A[j][i] * Yv[j][c];
        Yv[i][c] = s / A[i][i];
    }
    __syncthreads();
    for (int i = 0; i < 64; ++i) g_cov[g * 4096 + i * 64 + c] = Yv[i][c];
}

// ---------------- w0 = t*cov@a ; cw = cov@w0 ----------------
__global__ __launch_bounds__(256) void k_w0cw() {
    int g = blockIdx.x, tid = threadIdx.x;
    __shared__ float covs[64][65];
    __shared__ float as[64][17];
    __shared__ float w0s[64][17];
    for (int idx = tid; idx < 4096; idx += 256)
        covs[idx >> 6][idx & 63] = g_cov[g * 4096 + idx];
    for (int idx = tid; idx < 64 * CNY; idx += 256) {
        int i = idx >> 4, j = idx & 15;
        float s = 0.f;
#pragma unroll
        for (int sp = 0; sp < 8; ++sp) s += g_apart[sp][(g * 64 + i) * CNY + j];
        as[i][j] = s;
    }
    __syncthreads();
    float t = g_scal[1];
    int j = tid & 15, i0 = (tid >> 4) * 4;
#pragma unroll
    for (int ii = 0; ii < 4; ++ii) {
        float s = 0.f;
        for (int k = 0; k < 64; ++k) s = fmaf(covs[i0 + ii][k], as[k][j], s);
        w0s[i0 + ii][j] = t * s;
    }
    __syncthreads();
#pragma unroll
    for (int ii = 0; ii < 4; ++ii) {
        float s = 0.f;
        for (int k = 0; k < 64; ++k) s = fmaf(covs[i0 + ii][k], w0s[k][j], s);
        g_cw[(g * 64 + i0 + ii) * CNY + j] = s;
        g_w0[(g * 64 + i0 + ii) * CNY + j] = w0s[i0 + ii][j];
    }
}

// ---------------- softmax over groups -> p ----------------
__global__ __launch_bounds__(1024) void k_p() {
    int tid = threadIdx.x;
    int g = tid >> 4, j = tid & 15;
    float corr = 0.f;
    for (int i = 0; i < 64; ++i)
        corr = fmaf(g_w0[(g * 64 + i) * CNY + j], g_cw[(g * 64 + i) * CNY + j], corr);
    float t = g_scal[1];
    float lg = corr - t * g_ycss[j] - g_S[g];
    __shared__ float L[64][17];
    __shared__ float mx[16], sm[16];
    L[g][j] = lg;
    __syncthreads();
    if (tid < 16) {
        float m = -1e30f;
        for (int gg = 0; gg < 64; ++gg) m = fmaxf(m, L[gg][tid]);
        float s = 0.f;
        for (int gg = 0; gg < 64; ++gg) s += expf(L[gg][tid] - m);
        mx[tid] = m; sm[tid] = s;
    }
    __syncthreads();
    g_p[g * CNY + j] = expf(lg - mx[j]) / sm[j];
}

// ---------------- fold xmul into w and cov ----------------
__global__ void k_wprime() {
    int idx = blockIdx.x * 256 + threadIdx.x;
    int c = idx >> 4, j = idx & 15;
    g_w[idx] = g_w0[idx] * g_p[(c >> 6) * CNY + j] / g_xmul[c];
}
__global__ void k_covv() {
    int idx = blockIdx.x * 256 + threadIdx.x;
    int g = idx >> 12, i = (idx >> 6) & 63, j = idx & 63;
    g_covv[idx] = g_cov[idx] / (g_xmul[g * 64 + i] * g_xmul[g * 64 + j]);
}

// ---------------- fused predict ----------------
__global__ __launch_bounds__(128) void k_predict(const float* __restrict__ XQ,
                                                 float* __restrict__ out) {
    const int tid = threadIdx.x;
    const int r = tid >> 3, lane = tid & 7;
    const int row0 = blockIdx.x * 16;
    __shared__ float Xs[16][65];
    __shared__ float Cs[64][65];
    __shared__ float Ws[64][17];
    __shared__ float ps[16];
    float accy[CNY] = {};
    float v0 = 0.f, v1 = 0.f;
    for (int g = 0; g < CG; ++g) {
#pragma unroll
        for (int it = 0; it < 8; ++it) {
            int idx = tid + it * 128;
            Xs[idx >> 6][idx & 63] = XQ[(size_t)(row0 + (idx >> 6)) * CNH + g * 64 + (idx & 63)];
        }
#pragma unroll
        for (int it = 0; it < 32; ++it) {
            int idx = tid + it * 128;
            Cs[idx >> 6][idx & 63] = g_covv[g * 4096 + idx];
        }
#pragma unroll
        for (int it = 0; it < 8; ++it) {
            int idx = tid + it * 128;
            Ws[idx >> 4][idx & 15] = g_w[(g * 64 + (idx >> 4)) * CNY + (idx & 15)];
        }
        if (tid < 16) ps[tid] = g_p[g * CNY + tid];
        __syncthreads();
        float x[8];
#pragma unroll
        for (int ii = 0; ii < 8; ++ii) x[ii] = Xs[r][lane * 8 + ii];
#pragma unroll
        for (int ii = 0; ii < 8; ++ii)
#pragma unroll
            for (int j = 0; j < CNY; ++j)
                accy[j] = fmaf(x[ii], Ws[lane * 8 + ii][j], accy[j]);
        float s = 0.f;
        for (int jc = 0; jc < 64; ++jc) {
            float xj = Xs[r][jc];
            float q = 0.f;
#pragma unroll
            for (int ii = 0; ii < 8; ++ii) q = fmaf(Cs[lane * 8 + ii][jc], x[ii], q);
            s = fmaf(q, xj, s);
        }
        s += __shfl_xor_sync(0xffffffffu, s, 4);
        s += __shfl_xor_sync(0xffffffffu, s, 2);
        s += __shfl_xor_sync(0xffffffffu, s, 1);
        v0 = fmaf(s, ps[lane * 2 + 0], v0);
        v1 = fmaf(s, ps[lane * 2 + 1], v1);
        __syncthreads();
    }
#pragma unroll
    for (int j = 0; j < CNY; ++j) {
        accy[j] += __shfl_xor_sync(0xffffffffu, accy[j], 4);
        accy[j] += __shfl_xor_sync(0xffffffffu, accy[j], 2);
        accy[j] += __shfl_xor_sync(0xffffffffu, accy[j], 1);
    }
    const int row = row0 + r;
    const int j0 = lane * 2, j1 = j0 + 1;
    out[row * CNY + j0] = (accy[j0] + g_bmean[j0]) * g_ymul[j0];
    out[row * CNY + j1] = (accy[j1] + g_bmean[j1]) * g_ymul[j1];
    out[CN * CNY + row * CNY + j0] = sqrtf(fmaxf(v0, 0.f)) * g_ymul[j0];
    out[CN * CNY + row * CNY + j1] = sqrtf(fmaxf(v1, 0.f)) * g_ymul[j1];
}

// ---------------- launcher ----------------
extern "C" void kernel_launch(void* const* d_in, const int* in_sizes, int n_in,
                              void* d_out, int out_size) {
    const void* x  = d_in[0];
    const float* y = (const float*)d_in[1];
    const void* qx = d_in[2];
    const float* we = (const float*)d_in[3];
    const float* W1 = (const float*)d_in[4];
    const float* b1 = (const float*)d_in[5];
    const float* W2 = (const float*)d_in[6];
    const float* b2 = (const float*)d_in[7];
    const float* W3 = (const float*)d_in[8];
    const float* b3 = (const float*)d_in[9];
    const float* rp = (const float*)d_in[10];
    const float* tp = (const float*)d_in[11];
    float* out = (float*)d_out;

    bf16 *peh, *pel, *ph1h, *ph1l, *ph2h, *ph2l;
    bf16 *pW1h, *pW1l, *pW2h, *pW2l, *pW3h, *pW3l;
    float *pX;
    cudaGetSymbolAddress((void**)&peh,  g_eh);
    cudaGetSymbolAddress((void**)&pel,  g_el);
    cudaGetSymbolAddress((void**)&ph1h, g_h1h);
    cudaGetSymbolAddress((void**)&ph1l, g_h1l);
    cudaGetSymbolAddress((void**)&ph2h, g_h2h);
    cudaGetSymbolAddress((void**)&ph2l, g_h2l);
    cudaGetSymbolAddress((void**)&pW1h, g_W1h);
    cudaGetSymbolAddress((void**)&pW1l, g_W1l);
    cudaGetSymbolAddress((void**)&pW2h, g_W2h);
    cudaGetSymbolAddress((void**)&pW2l, g_W2l);
    cudaGetSymbolAddress((void**)&pW3h, g_W3h);
    cudaGetSymbolAddress((void**)&pW3l, g_W3l);
    cudaGetSymbolAddress((void**)&pX,  g_X);
    float* pXQ = pX + (size_t)CN * CNH;

    cudaFuncSetAttribute(k_gemm_bf16, cudaFuncAttributeMaxDynamicSharedMemorySize, 4 * GSTAGE);

    k_detect<<<1, 256>>>((const int*)x, in_sizes[0]);
    k_scal<<<1, 1>>>(rp, tp);
    k_ystats<<<16, 256>>>(y);

    // split weights
    k_split<<<(CH * CNIN / 4 + 255) / 256, 256>>>((const float4*)W1, pW1h, pW1l, CH * CNIN / 4);
    k_split<<<(CH * CH   / 4 + 255) / 256, 256>>>((const float4*)W2, pW2h, pW2l, CH * CH / 4);
    k_split<<<(CNH * CH  / 4 + 255) / 256, 256>>>((const float4*)W3, pW3h, pW3l, CNH * CH / 4);

    // merged gather + MLP (train rows 0..2047, query rows 2048..4095)
    const int gatherBlocks = (CN2 * (CNIN / 4) + 255) / 256;
    k_gather<<<gatherBlocks, 256>>>(x, qx, (const float4*)we, peh, pel);
    k_gemm_bf16<<<dim3(CH / 128, CN2 / 128), 256, 4 * GSTAGE>>>(peh, pel, pW1h, pW1l, b1, nullptr, ph1h, ph1l, CN2, CH, CNIN, 1);
    k_gemm_bf16<<<dim3(CH / 128, CN2 / 128), 256, 4 * GSTAGE>>>(ph1h, ph1l, pW2h, pW2l, b2, nullptr, ph2h, ph2l, CN2, CH, CH, 1);
    k_gemm_bf16<<<dim3(CNH / 128, CN2 / 128), 256, 4 * GSTAGE>>>(ph2h, ph2l, pW3h, pW3l, b3, pX, nullptr, nullptr, CN2, CNH, CH, 0);

    // ridge learn
    k_xstats<<<CNH / 256, 256>>>();
    k_cov<<<dim3(CG, 4), 256>>>();
    k_apart<<<dim3(CNH / 256, 8), 256>>>();
    k_chol<<<CG, 64>>>();
    k_w0cw<<<CG, 256>>>();
    k_p<<<1, 1024>>>();
    k_wprime<<<(CNH * CNY) / 256, 256>>>();
    k_covv<<<(CG * 64 * 64) / 256, 256>>>();

    // fused predict (qy + qy_std)
    k_predict<<<CN / 16, 128>>>(pXQ, out);
}